// round 6
// baseline (speedup 1.0000x reference)
#include <cuda_runtime.h>
#include <mma.h>
#include <cstdint>

using namespace nvcuda;

// Problem shapes (fixed by the reference)
#define BB 4
#define LL 4096
#define DM 1024
#define DI 2048

// ---------------------------------------------------------------------------
// Scratch (device globals — no allocation allowed in kernel_launch)
// ---------------------------------------------------------------------------
__device__ float g_xz [(size_t)BB * LL * (2 * DI)];  // in_proj output [B,L,4096]
__device__ float g_xc [(size_t)BB * LL * DI];        // conv+silu output
__device__ float g_dtp[(size_t)BB * LL * DI];        // dt pre-activation
__device__ float g_Bpp[(size_t)BB * LL * DI];        // B pre-activation
__device__ float g_Cpp[(size_t)BB * LL * DI];        // C pre-activation
__device__ float g_y  [(size_t)BB * LL * DI];        // gated scan output

// ---------------------------------------------------------------------------
// GEMM: C[M,N] = A[M,K] * W[N,K]^T   (tf32 tensor cores, fp32 accumulate)
//   A row-major [M,K], W row-major [N,K] (== B col-major), C row-major [M,N]
//   Block tile 128x128x32, 8 warps (4 along M x 2 along N), warp tile 32x64.
//   Double-buffered cp.async, smem stride 36 (16B-aligned rows, conflict-free).
// ---------------------------------------------------------------------------
#define BM 128
#define BN 128
#define BKK 32
#define SST 36
#define GEMM_SMEM (2 * (BM + BN) * SST * (int)sizeof(float))  // 73728 B

__device__ __forceinline__ void cp16(float* dst, const float* src) {
    unsigned s = (unsigned)__cvta_generic_to_shared(dst);
    asm volatile("cp.async.cg.shared.global [%0], [%1], 16;\n" ::"r"(s), "l"(src));
}

__device__ __forceinline__ void load_tiles(float* Asd, float* Bsd,
                                           const float* Ag, const float* Wg,
                                           int K, int tid) {
    // 128 rows x 32 floats each for A and B: 1024 16B chunks / 256 threads = 4 each
#pragma unroll
    for (int i = 0; i < 4; i++) {
        int chunk = tid + i * 256;          // 0..1023
        int row   = chunk >> 3;             // 0..127
        int col   = (chunk & 7) << 2;       // 0,4,...,28
        cp16(Asd + row * SST + col, Ag + (size_t)row * K + col);
        cp16(Bsd + row * SST + col, Wg + (size_t)row * K + col);
    }
}

__global__ __launch_bounds__(256) void gemm_tf32(const float* __restrict__ A,
                                                 const float* __restrict__ W,
                                                 float* __restrict__ C,
                                                 int K, int N) {
    extern __shared__ float smem[];
    float* As = smem;                     // [2][BM][SST]
    float* Bs = smem + 2 * BM * SST;      // [2][BN][SST]

    const int tid   = threadIdx.x;
    const int mBase = blockIdx.y * BM;
    const int nBase = blockIdx.x * BN;
    const int warp  = tid >> 5;
    const int wm    = warp & 3;           // warp row  (0..3) -> 32 M-rows
    const int wn    = warp >> 2;          // warp col  (0..1) -> 64 N-cols

    wmma::fragment<wmma::accumulator, 16, 16, 8, float> acc[2][4];
#pragma unroll
    for (int i = 0; i < 2; i++)
#pragma unroll
        for (int j = 0; j < 4; j++) wmma::fill_fragment(acc[i][j], 0.0f);

    const float* Abase = A + (size_t)mBase * K;
    const float* Wbase = W + (size_t)nBase * K;
    const int KT = K / BKK;

    load_tiles(As, Bs, Abase, Wbase, K, tid);
    asm volatile("cp.async.commit_group;\n");

    for (int kt = 0; kt < KT; kt++) {
        if (kt + 1 < KT) {
            int s = (kt + 1) & 1;
            load_tiles(As + s * BM * SST, Bs + s * BN * SST,
                       Abase + (size_t)(kt + 1) * BKK,
                       Wbase + (size_t)(kt + 1) * BKK, K, tid);
            asm volatile("cp.async.commit_group;\n");
            asm volatile("cp.async.wait_group 1;\n");
        } else {
            asm volatile("cp.async.wait_group 0;\n");
        }
        __syncthreads();

        const float* Asd = As + (kt & 1) * BM * SST;
        const float* Bsd = Bs + (kt & 1) * BN * SST;

#pragma unroll
        for (int kk = 0; kk < BKK / 8; kk++) {
            wmma::fragment<wmma::matrix_a, 16, 16, 8, wmma::precision::tf32,
                           wmma::row_major> af[2];
            wmma::fragment<wmma::matrix_b, 16, 16, 8, wmma::precision::tf32,
                           wmma::col_major> bf[4];
#pragma unroll
            for (int i = 0; i < 2; i++) {
                wmma::load_matrix_sync(af[i], Asd + (wm * 32 + i * 16) * SST + kk * 8, SST);
#pragma unroll
                for (int t = 0; t < af[i].num_elements; t++)
                    af[i].x[t] = wmma::__float_to_tf32(af[i].x[t]);
            }
#pragma unroll
            for (int j = 0; j < 4; j++) {
                wmma::load_matrix_sync(bf[j], Bsd + (wn * 64 + j * 16) * SST + kk * 8, SST);
#pragma unroll
                for (int t = 0; t < bf[j].num_elements; t++)
                    bf[j].x[t] = wmma::__float_to_tf32(bf[j].x[t]);
            }
#pragma unroll
            for (int i = 0; i < 2; i++)
#pragma unroll
                for (int j = 0; j < 4; j++)
                    wmma::mma_sync(acc[i][j], af[i], bf[j], acc[i][j]);
        }
        __syncthreads();
    }

#pragma unroll
    for (int i = 0; i < 2; i++)
#pragma unroll
        for (int j = 0; j < 4; j++) {
            size_t row = (size_t)(mBase + wm * 32 + i * 16);
            int    col = nBase + wn * 64 + j * 16;
            wmma::store_matrix_sync(C + row * N + col, acc[i][j], N,
                                    wmma::mem_row_major);
        }
}

// ---------------------------------------------------------------------------
// Depthwise causal conv1d (k=4) + bias + SiLU.  Input x1 = xz[..., 0:DI].
// ---------------------------------------------------------------------------
__global__ void conv_silu_kernel(const float* __restrict__ xz,
                                 const float* __restrict__ Wc,
                                 const float* __restrict__ bc,
                                 float* __restrict__ xc) {
    size_t idx = (size_t)blockIdx.x * blockDim.x + threadIdx.x;
    if (idx >= (size_t)BB * LL * DI) return;
    int d     = (int)(idx % DI);
    size_t bl = idx / DI;                 // b*LL + l
    int l     = (int)(bl % LL);

    const float* xp = xz + bl * (size_t)(2 * DI) + d;  // x1[b,l,d]
    float acc = bc[d];
#pragma unroll
    for (int j = 0; j < 4; j++) {
        int ll = l - 3 + j;
        if (ll >= 0) acc += Wc[d * 4 + j] * xp[(ptrdiff_t)(j - 3) * (2 * DI)];
    }
    xc[idx] = acc * (1.0f / (1.0f + __expf(-acc)));
}

// ---------------------------------------------------------------------------
// Fused SSM scan. One thread per (b, d) sequence: applies softplus/sigmoid/
// tanh/silu, runs h_t = exp(la_t)*h_{t-1} + beta_t, writes y = h*C*silu(z).
// Mathematically identical to the reference's stabilized cumsum form.
// ---------------------------------------------------------------------------
__global__ void scan_kernel(const float* __restrict__ xz,
                            const float* __restrict__ xc,
                            const float* __restrict__ dtp,
                            const float* __restrict__ Bp,
                            const float* __restrict__ Cp,
                            const float* __restrict__ bdt,
                            const float* __restrict__ A_log,
                            float* __restrict__ y) {
    int t = blockIdx.x * blockDim.x + threadIdx.x;   // 0 .. BB*DI-1
    if (t >= BB * DI) return;
    int d = t % DI;
    int b = t / DI;

    const float bd = bdt[d];
    const float Ad = -expf(A_log[d]);

    size_t off  = (size_t)b * LL * DI + d;
    size_t zoff = (size_t)b * LL * (2 * DI) + DI + d;

    float h = 0.0f, uprev = 0.0f;
    for (int l = 0; l < LL; l++) {
        float xv  = dtp[off] + bd;
        float dtv = (xv > 20.0f) ? xv : log1pf(__expf(xv));      // softplus
        float la  = fminf(fmaxf(Ad * dtv, -10.0f), -0.0001f);    // clip
        float a   = __expf(la);

        float Bt  = 1.0f / (1.0f + __expf(-Bp[off]));            // sigmoid
        float u   = xc[off] * Bt;

        h = a * h + dtv * 0.5f * (uprev + u);                    // trapezoid
        uprev = u;

        float Ct  = tanhf(Cp[off]);
        float zv  = xz[zoff];
        float sz  = zv * (1.0f / (1.0f + __expf(-zv)));          // silu(z)

        y[off] = h * Ct * sz;

        off  += DI;
        zoff += 2 * DI;
    }
}

// ---------------------------------------------------------------------------
// Launch
// ---------------------------------------------------------------------------
extern "C" void kernel_launch(void* const* d_in, const int* in_sizes, int n_in,
                              void* d_out, int out_size) {
    const float* x     = (const float*)d_in[0];
    const float* Wi    = (const float*)d_in[1];
    const float* Wconv = (const float*)d_in[2];
    const float* bconv = (const float*)d_in[3];
    const float* Wdt   = (const float*)d_in[4];
    const float* bdt   = (const float*)d_in[5];
    const float* WB    = (const float*)d_in[6];
    const float* WC    = (const float*)d_in[7];
    const float* Wo    = (const float*)d_in[8];
    const float* A_log = (const float*)d_in[9];
    float*       out   = (float*)d_out;

    float *xz, *xc, *dtp, *Bpp, *Cpp, *yb;
    cudaGetSymbolAddress((void**)&xz,  g_xz);
    cudaGetSymbolAddress((void**)&xc,  g_xc);
    cudaGetSymbolAddress((void**)&dtp, g_dtp);
    cudaGetSymbolAddress((void**)&Bpp, g_Bpp);
    cudaGetSymbolAddress((void**)&Cpp, g_Cpp);
    cudaGetSymbolAddress((void**)&yb,  g_y);

    cudaFuncSetAttribute(gemm_tf32, cudaFuncAttributeMaxDynamicSharedMemorySize,
                         GEMM_SMEM);

    const int M = BB * LL;               // 16384
    dim3 blk(256);

    // 1) in_proj: xz[M, 4096] = x[M,1024] @ Wi[4096,1024]^T
    gemm_tf32<<<dim3((2 * DI) / BN, M / BM), blk, GEMM_SMEM>>>(x, Wi, xz, DM, 2 * DI);

    // 2) depthwise causal conv + SiLU
    {
        size_t total = (size_t)M * DI;
        conv_silu_kernel<<<(unsigned)(total / 256), 256>>>(xz, Wconv, bconv, xc);
    }

    // 3) dt/B/C projections: [M,2048] @ [2048,2048]^T
    gemm_tf32<<<dim3(DI / BN, M / BM), blk, GEMM_SMEM>>>(xc, Wdt, dtp, DI, DI);
    gemm_tf32<<<dim3(DI / BN, M / BM), blk, GEMM_SMEM>>>(xc, WB,  Bpp, DI, DI);
    gemm_tf32<<<dim3(DI / BN, M / BM), blk, GEMM_SMEM>>>(xc, WC,  Cpp, DI, DI);

    // 4) fused activations + sequential scan + gating -> y
    scan_kernel<<<(BB * DI) / 128, 128>>>(xz, xc, dtp, Bpp, Cpp, bdt, A_log, yb);

    // 5) out_proj: out[M,1024] = y[M,2048] @ Wo[1024,2048]^T
    gemm_tf32<<<dim3(DM / BN, M / BM), blk, GEMM_SMEM>>>(yb, Wo, out, DI, DM);
}

// round 7
// speedup vs baseline: 1.0028x; 1.0028x over previous
#include <cuda_runtime.h>
#include <mma.h>
#include <cstdint>

using namespace nvcuda;

// Problem shapes (fixed by the reference)
#define BB 4
#define LL 4096
#define DM 1024
#define DI 2048

// ---------------------------------------------------------------------------
// Scratch (device globals — no allocation allowed in kernel_launch)
// ---------------------------------------------------------------------------
__device__ float g_xz [(size_t)BB * LL * (2 * DI)];  // in_proj output [B,L,4096]
__device__ float g_xc [(size_t)BB * LL * DI];        // conv+silu output
__device__ float g_dtp[(size_t)BB * LL * DI];        // dt pre-activation
__device__ float g_Bpp[(size_t)BB * LL * DI];        // B pre-activation
__device__ float g_Cpp[(size_t)BB * LL * DI];        // C pre-activation
__device__ float g_y  [(size_t)BB * LL * DI];        // gated scan output

// ---------------------------------------------------------------------------
// GEMM: C[M,N] = A[M,K] * W[N,K]^T   (tf32 tensor cores, fp32 accumulate)
//   A row-major [M,K], W row-major [N,K] (== B col-major), C row-major [M,N]
//   Block tile 128x128x32, 8 warps (4 along M x 2 along N), warp tile 32x64.
//   Double-buffered cp.async, smem stride 36 (16B-aligned rows, conflict-free).
// ---------------------------------------------------------------------------
#define BM 128
#define BN 128
#define BKK 32
#define SST 36
#define GEMM_SMEM (2 * (BM + BN) * SST * (int)sizeof(float))  // 73728 B

__device__ __forceinline__ void cp16(float* dst, const float* src) {
    unsigned s = (unsigned)__cvta_generic_to_shared(dst);
    asm volatile("cp.async.cg.shared.global [%0], [%1], 16;\n" ::"r"(s), "l"(src));
}

__device__ __forceinline__ void load_tiles(float* Asd, float* Bsd,
                                           const float* Ag, const float* Wg,
                                           int K, int tid) {
    // 128 rows x 32 floats each for A and B: 1024 16B chunks / 256 threads = 4 each
#pragma unroll
    for (int i = 0; i < 4; i++) {
        int chunk = tid + i * 256;          // 0..1023
        int row   = chunk >> 3;             // 0..127
        int col   = (chunk & 7) << 2;       // 0,4,...,28
        cp16(Asd + row * SST + col, Ag + (size_t)row * K + col);
        cp16(Bsd + row * SST + col, Wg + (size_t)row * K + col);
    }
}

__global__ __launch_bounds__(256) void gemm_tf32(const float* __restrict__ A,
                                                 const float* __restrict__ W,
                                                 float* __restrict__ C,
                                                 int K, int N) {
    extern __shared__ float smem[];
    float* As = smem;                     // [2][BM][SST]
    float* Bs = smem + 2 * BM * SST;      // [2][BN][SST]

    const int tid   = threadIdx.x;
    const int mBase = blockIdx.y * BM;
    const int nBase = blockIdx.x * BN;
    const int warp  = tid >> 5;
    const int wm    = warp & 3;           // warp row  (0..3) -> 32 M-rows
    const int wn    = warp >> 2;          // warp col  (0..1) -> 64 N-cols

    wmma::fragment<wmma::accumulator, 16, 16, 8, float> acc[2][4];
#pragma unroll
    for (int i = 0; i < 2; i++)
#pragma unroll
        for (int j = 0; j < 4; j++) wmma::fill_fragment(acc[i][j], 0.0f);

    const float* Abase = A + (size_t)mBase * K;
    const float* Wbase = W + (size_t)nBase * K;
    const int KT = K / BKK;

    load_tiles(As, Bs, Abase, Wbase, K, tid);
    asm volatile("cp.async.commit_group;\n");

    for (int kt = 0; kt < KT; kt++) {
        if (kt + 1 < KT) {
            int s = (kt + 1) & 1;
            load_tiles(As + s * BM * SST, Bs + s * BN * SST,
                       Abase + (size_t)(kt + 1) * BKK,
                       Wbase + (size_t)(kt + 1) * BKK, K, tid);
            asm volatile("cp.async.commit_group;\n");
            asm volatile("cp.async.wait_group 1;\n");
        } else {
            asm volatile("cp.async.wait_group 0;\n");
        }
        __syncthreads();

        const float* Asd = As + (kt & 1) * BM * SST;
        const float* Bsd = Bs + (kt & 1) * BN * SST;

#pragma unroll
        for (int kk = 0; kk < BKK / 8; kk++) {
            wmma::fragment<wmma::matrix_a, 16, 16, 8, wmma::precision::tf32,
                           wmma::row_major> af[2];
            wmma::fragment<wmma::matrix_b, 16, 16, 8, wmma::precision::tf32,
                           wmma::col_major> bf[4];
#pragma unroll
            for (int i = 0; i < 2; i++) {
                wmma::load_matrix_sync(af[i], Asd + (wm * 32 + i * 16) * SST + kk * 8, SST);
#pragma unroll
                for (int t = 0; t < af[i].num_elements; t++)
                    af[i].x[t] = wmma::__float_to_tf32(af[i].x[t]);
            }
#pragma unroll
            for (int j = 0; j < 4; j++) {
                wmma::load_matrix_sync(bf[j], Bsd + (wn * 64 + j * 16) * SST + kk * 8, SST);
#pragma unroll
                for (int t = 0; t < bf[j].num_elements; t++)
                    bf[j].x[t] = wmma::__float_to_tf32(bf[j].x[t]);
            }
#pragma unroll
            for (int i = 0; i < 2; i++)
#pragma unroll
                for (int j = 0; j < 4; j++)
                    wmma::mma_sync(acc[i][j], af[i], bf[j], acc[i][j]);
        }
        __syncthreads();
    }

#pragma unroll
    for (int i = 0; i < 2; i++)
#pragma unroll
        for (int j = 0; j < 4; j++) {
            size_t row = (size_t)(mBase + wm * 32 + i * 16);
            int    col = nBase + wn * 64 + j * 16;
            wmma::store_matrix_sync(C + row * N + col, acc[i][j], N,
                                    wmma::mem_row_major);
        }
}

// ---------------------------------------------------------------------------
// Depthwise causal conv1d (k=4) + bias + SiLU.  Input x1 = xz[..., 0:DI].
// ---------------------------------------------------------------------------
__global__ void conv_silu_kernel(const float* __restrict__ xz,
                                 const float* __restrict__ Wc,
                                 const float* __restrict__ bc,
                                 float* __restrict__ xc) {
    size_t idx = (size_t)blockIdx.x * blockDim.x + threadIdx.x;
    if (idx >= (size_t)BB * LL * DI) return;
    int d     = (int)(idx % DI);
    size_t bl = idx / DI;                 // b*LL + l
    int l     = (int)(bl % LL);

    const float* xp = xz + bl * (size_t)(2 * DI) + d;  // x1[b,l,d]
    float acc = bc[d];
#pragma unroll
    for (int j = 0; j < 4; j++) {
        int ll = l - 3 + j;
        if (ll >= 0) acc += Wc[d * 4 + j] * xp[(ptrdiff_t)(j - 3) * (2 * DI)];
    }
    xc[idx] = acc * (1.0f / (1.0f + __expf(-acc)));
}

// ---------------------------------------------------------------------------
// Fused SSM scan. One thread per (b, d) sequence: applies softplus/sigmoid/
// tanh/silu, runs h_t = exp(la_t)*h_{t-1} + beta_t, writes y = h*C*silu(z).
// Mathematically identical to the reference's stabilized cumsum form.
// ---------------------------------------------------------------------------
__global__ void scan_kernel(const float* __restrict__ xz,
                            const float* __restrict__ xc,
                            const float* __restrict__ dtp,
                            const float* __restrict__ Bp,
                            const float* __restrict__ Cp,
                            const float* __restrict__ bdt,
                            const float* __restrict__ A_log,
                            float* __restrict__ y) {
    int t = blockIdx.x * blockDim.x + threadIdx.x;   // 0 .. BB*DI-1
    if (t >= BB * DI) return;
    int d = t % DI;
    int b = t / DI;

    const float bd = bdt[d];
    const float Ad = -expf(A_log[d]);

    size_t off  = (size_t)b * LL * DI + d;
    size_t zoff = (size_t)b * LL * (2 * DI) + DI + d;

    float h = 0.0f, uprev = 0.0f;
    for (int l = 0; l < LL; l++) {
        float xv  = dtp[off] + bd;
        float dtv = (xv > 20.0f) ? xv : log1pf(__expf(xv));      // softplus
        float la  = fminf(fmaxf(Ad * dtv, -10.0f), -0.0001f);    // clip
        float a   = __expf(la);

        float Bt  = 1.0f / (1.0f + __expf(-Bp[off]));            // sigmoid
        float u   = xc[off] * Bt;

        h = a * h + dtv * 0.5f * (uprev + u);                    // trapezoid
        uprev = u;

        float Ct  = tanhf(Cp[off]);
        float zv  = xz[zoff];
        float sz  = zv * (1.0f / (1.0f + __expf(-zv)));          // silu(z)

        y[off] = h * Ct * sz;

        off  += DI;
        zoff += 2 * DI;
    }
}

// ---------------------------------------------------------------------------
// Launch
// ---------------------------------------------------------------------------
extern "C" void kernel_launch(void* const* d_in, const int* in_sizes, int n_in,
                              void* d_out, int out_size) {
    const float* x     = (const float*)d_in[0];
    const float* Wi    = (const float*)d_in[1];
    const float* Wconv = (const float*)d_in[2];
    const float* bconv = (const float*)d_in[3];
    const float* Wdt   = (const float*)d_in[4];
    const float* bdt   = (const float*)d_in[5];
    const float* WB    = (const float*)d_in[6];
    const float* WC    = (const float*)d_in[7];
    const float* Wo    = (const float*)d_in[8];
    const float* A_log = (const float*)d_in[9];
    float*       out   = (float*)d_out;

    float *xz, *xc, *dtp, *Bpp, *Cpp, *yb;
    cudaGetSymbolAddress((void**)&xz,  g_xz);
    cudaGetSymbolAddress((void**)&xc,  g_xc);
    cudaGetSymbolAddress((void**)&dtp, g_dtp);
    cudaGetSymbolAddress((void**)&Bpp, g_Bpp);
    cudaGetSymbolAddress((void**)&Cpp, g_Cpp);
    cudaGetSymbolAddress((void**)&yb,  g_y);

    cudaFuncSetAttribute(gemm_tf32, cudaFuncAttributeMaxDynamicSharedMemorySize,
                         GEMM_SMEM);

    const int M = BB * LL;               // 16384
    dim3 blk(256);

    // 1) in_proj: xz[M, 4096] = x[M,1024] @ Wi[4096,1024]^T
    gemm_tf32<<<dim3((2 * DI) / BN, M / BM), blk, GEMM_SMEM>>>(x, Wi, xz, DM, 2 * DI);

    // 2) depthwise causal conv + SiLU
    {
        size_t total = (size_t)M * DI;
        conv_silu_kernel<<<(unsigned)(total / 256), 256>>>(xz, Wconv, bconv, xc);
    }

    // 3) dt/B/C projections: [M,2048] @ [2048,2048]^T
    gemm_tf32<<<dim3(DI / BN, M / BM), blk, GEMM_SMEM>>>(xc, Wdt, dtp, DI, DI);
    gemm_tf32<<<dim3(DI / BN, M / BM), blk, GEMM_SMEM>>>(xc, WB,  Bpp, DI, DI);
    gemm_tf32<<<dim3(DI / BN, M / BM), blk, GEMM_SMEM>>>(xc, WC,  Cpp, DI, DI);

    // 4) fused activations + sequential scan + gating -> y
    scan_kernel<<<(BB * DI) / 128, 128>>>(xz, xc, dtp, Bpp, Cpp, bdt, A_log, yb);

    // 5) out_proj: out[M,1024] = y[M,2048] @ Wo[1024,2048]^T
    gemm_tf32<<<dim3(DM / BN, M / BM), blk, GEMM_SMEM>>>(yb, Wo, out, DI, DM);
}

// round 9
// speedup vs baseline: 1.6035x; 1.5990x over previous
#include <cuda_runtime.h>
#include <mma.h>
#include <cstdint>

using namespace nvcuda;

#define BB 4
#define LL 4096
#define DM 1024
#define DI 2048
#define MTOT (BB * LL)          // 16384
#define NCHUNK 16
#define LCH (LL / NCHUNK)       // 256

// ---------------------------------------------------------------------------
// Scratch (device globals; allocation is forbidden in kernel_launch)
// ---------------------------------------------------------------------------
__device__ __align__(1024) float g_xz  [(size_t)MTOT * (2 * DI)]; // in_proj out
__device__ __align__(1024) float g_xc  [(size_t)MTOT * DI];       // conv out fp32
__device__ __align__(1024) float g_xct [(size_t)MTOT * DI];       // conv out tf32
__device__ __align__(1024) float g_dtp [(size_t)MTOT * DI];
__device__ __align__(1024) float g_Bpp [(size_t)MTOT * DI];
__device__ __align__(1024) float g_Cpp [(size_t)MTOT * DI];
__device__ __align__(1024) float g_yt  [(size_t)MTOT * DI];       // scan out tf32

__device__ __align__(1024) float g_xt  [(size_t)MTOT * DM];       // x tf32
__device__ __align__(1024) float g_Wit [(size_t)2 * DI * DM];
__device__ __align__(1024) float g_Wdtt[(size_t)DI * DI];
__device__ __align__(1024) float g_WBt [(size_t)DI * DI];
__device__ __align__(1024) float g_WCt [(size_t)DI * DI];
__device__ __align__(1024) float g_Wot [(size_t)DM * DI];

__device__ float g_Aprod[BB * NCHUNK * DI];
__device__ float g_Hend [BB * NCHUNK * DI];
__device__ float g_Carry[BB * NCHUNK * DI];

// ---------------------------------------------------------------------------
// helpers
// ---------------------------------------------------------------------------
__device__ __forceinline__ float tf32r(float v) {
    float r;
    asm("cvt.rna.tf32.f32 %0, %1;" : "=f"(r) : "f"(v));
    return r;
}

__device__ __forceinline__ void cp16(float* dst, const float* src) {
    unsigned s = (unsigned)__cvta_generic_to_shared(dst);
    asm volatile("cp.async.cg.shared.global [%0], [%1], 16;" ::"r"(s), "l"(src));
}

// ---------------------------------------------------------------------------
// GEMM: C[M,N] = A[M,K] * W[N,K]^T  (tf32 HMMA, fp32 accumulate)
//   Inputs pre-rounded to tf32 -> no cvt in the mainloop.
//   128x128x32 tiles, 8 warps (4x2), warp tile 32x64, 4-stage cp.async.
// ---------------------------------------------------------------------------
#define BM 128
#define BN 128
#define BK 32
#define SST 36
#define NSTG 4
#define STAGEF ((BM + BN) * SST)                 // floats per stage
#define GEMM_SMEM (NSTG * STAGEF * (int)sizeof(float))  // 147456 B

__device__ __forceinline__ void load_stage(float* sbase, const float* A,
                                           const float* W, int kt, int K,
                                           int mBase, int nBase, int tid) {
    const float* Ab = A + (size_t)mBase * K + (size_t)kt * BK;
    const float* Wb = W + (size_t)nBase * K + (size_t)kt * BK;
#pragma unroll
    for (int i = 0; i < 8; i++) {
        int chunk = tid + i * 256;          // 0..2047
        int tile  = chunk >> 10;            // 0: A, 1: W
        int rem   = chunk & 1023;
        int row   = rem >> 3;               // 0..127
        int col   = (rem & 7) << 2;         // 0..28
        const float* src = (tile ? Wb : Ab) + (size_t)row * K + col;
        float* dst = sbase + tile * (BM * SST) + row * SST + col;
        cp16(dst, src);
    }
    asm volatile("cp.async.commit_group;" ::: "memory");
}

__global__ __launch_bounds__(256, 1) void gemm_tf32(const float* __restrict__ A,
                                                    const float* __restrict__ W,
                                                    float* __restrict__ C,
                                                    int K, int N) {
    extern __shared__ float smem[];
    const int tid   = threadIdx.x;
    const int warp  = tid >> 5;
    const int wm    = warp & 3;
    const int wn    = warp >> 2;
    const int mBase = blockIdx.y * BM;
    const int nBase = blockIdx.x * BN;

    wmma::fragment<wmma::accumulator, 16, 16, 8, float> acc[2][4];
#pragma unroll
    for (int i = 0; i < 2; i++)
#pragma unroll
        for (int j = 0; j < 4; j++) wmma::fill_fragment(acc[i][j], 0.0f);

    const int KT = K / BK;

    // prologue: 3 stages in flight
    load_stage(smem + 0 * STAGEF, A, W, 0, K, mBase, nBase, tid);
    load_stage(smem + 1 * STAGEF, A, W, 1, K, mBase, nBase, tid);
    load_stage(smem + 2 * STAGEF, A, W, 2, K, mBase, nBase, tid);

    for (int kt = 0; kt < KT; kt++) {
        int rem = KT - 1 - kt;  // groups that may stay pending
        if (rem >= 2)      asm volatile("cp.async.wait_group 2;" ::: "memory");
        else if (rem == 1) asm volatile("cp.async.wait_group 1;" ::: "memory");
        else               asm volatile("cp.async.wait_group 0;" ::: "memory");
        __syncthreads();

        if (kt + 3 < KT)
            load_stage(smem + ((kt + 3) & 3) * STAGEF, A, W, kt + 3, K,
                       mBase, nBase, tid);

        const float* As = smem + (kt & 3) * STAGEF;
        const float* Bs = As + BM * SST;

#pragma unroll
        for (int kk = 0; kk < BK / 8; kk++) {
            wmma::fragment<wmma::matrix_a, 16, 16, 8, wmma::precision::tf32,
                           wmma::row_major> af[2];
            wmma::fragment<wmma::matrix_b, 16, 16, 8, wmma::precision::tf32,
                           wmma::col_major> bf[4];
#pragma unroll
            for (int i = 0; i < 2; i++)
                wmma::load_matrix_sync(af[i], As + (wm * 32 + i * 16) * SST + kk * 8, SST);
#pragma unroll
            for (int j = 0; j < 4; j++)
                wmma::load_matrix_sync(bf[j], Bs + (wn * 64 + j * 16) * SST + kk * 8, SST);
#pragma unroll
            for (int i = 0; i < 2; i++)
#pragma unroll
                for (int j = 0; j < 4; j++)
                    wmma::mma_sync(acc[i][j], af[i], bf[j], acc[i][j]);
        }
    }

#pragma unroll
    for (int i = 0; i < 2; i++)
#pragma unroll
        for (int j = 0; j < 4; j++) {
            size_t row = (size_t)(mBase + wm * 32 + i * 16);
            int    col = nBase + wn * 64 + j * 16;
            wmma::store_matrix_sync(C + row * N + col, acc[i][j], N,
                                    wmma::mem_row_major);
        }
}

// ---------------------------------------------------------------------------
// tf32 pre-round (RNA) — producers for GEMM operands
// ---------------------------------------------------------------------------
__global__ void round_kernel(const float* __restrict__ in,
                             float* __restrict__ out, size_t n) {
    size_t i = ((size_t)blockIdx.x * blockDim.x + threadIdx.x) * 4;
    if (i >= n) return;
    float4 v = *(const float4*)(in + i);
    v.x = tf32r(v.x); v.y = tf32r(v.y); v.z = tf32r(v.z); v.w = tf32r(v.w);
    *(float4*)(out + i) = v;
}

// ---------------------------------------------------------------------------
// depthwise causal conv1d (k=4) + bias + SiLU
// ---------------------------------------------------------------------------
__global__ void conv_silu_kernel(const float* __restrict__ xz,
                                 const float* __restrict__ Wc,
                                 const float* __restrict__ bc,
                                 float* __restrict__ xc,
                                 float* __restrict__ xct) {
    size_t idx = (size_t)blockIdx.x * blockDim.x + threadIdx.x;
    if (idx >= (size_t)MTOT * DI) return;
    int d     = (int)(idx % DI);
    size_t bl = idx / DI;
    int l     = (int)(bl % LL);

    const float* xp = xz + bl * (size_t)(2 * DI) + d;
    float acc = bc[d];
#pragma unroll
    for (int j = 0; j < 4; j++) {
        int ll = l - 3 + j;
        if (ll >= 0) acc += Wc[d * 4 + j] * xp[(ptrdiff_t)(j - 3) * (2 * DI)];
    }
    float r = acc * (1.0f / (1.0f + __expf(-acc)));
    xc[idx]  = r;
    xct[idx] = tf32r(r);
}

// ---------------------------------------------------------------------------
// Chunked SSM scan (3 passes); arithmetic identical to the serial recurrence
//   h_t = exp(clip(A*softplus(dtp_t+bdt))) * h_{t-1} + dt_t*0.5*(u_{t-1}+u_t)
// ---------------------------------------------------------------------------
__device__ __forceinline__ float sp_f(float x) {
    return (x > 20.0f) ? x : log1pf(__expf(x));
}
__device__ __forceinline__ float sig_f(float x) { return 1.0f / (1.0f + __expf(-x)); }

__global__ void scan_chunks(const float* __restrict__ xc,
                            const float* __restrict__ dtp,
                            const float* __restrict__ Bp,
                            const float* __restrict__ bdt,
                            const float* __restrict__ A_log,
                            float* __restrict__ Aprod, float* __restrict__ Hend) {
    int idx = blockIdx.x * blockDim.x + threadIdx.x;    // BB*NCHUNK*DI
    if (idx >= BB * NCHUNK * DI) return;
    int d  = idx % DI;
    int bc = idx / DI;
    int c  = bc % NCHUNK;
    int b  = bc / NCHUNK;

    const float bd = bdt[d];
    const float Ad = -expf(A_log[d]);
    int l0 = c * LCH;
    size_t off = ((size_t)b * LL + l0) * DI + d;

    float uprev = 0.0f;
    if (l0 > 0) uprev = xc[off - DI] * sig_f(Bp[off - DI]);

    float h = 0.0f, A = 1.0f;
    for (int l = 0; l < LCH; l++) {
        float dtv = sp_f(dtp[off] + bd);
        float la  = fminf(fmaxf(Ad * dtv, -10.0f), -0.0001f);
        float a   = __expf(la);
        float u   = xc[off] * sig_f(Bp[off]);
        h = a * h + dtv * 0.5f * (uprev + u);
        A *= a;
        uprev = u;
        off += DI;
    }
    Aprod[idx] = A;
    Hend[idx]  = h;
}

__global__ void scan_carry(const float* __restrict__ Aprod,
                           const float* __restrict__ Hend,
                           float* __restrict__ Carry) {
    int t = blockIdx.x * blockDim.x + threadIdx.x;      // BB*DI
    if (t >= BB * DI) return;
    int d = t % DI, b = t / DI;
    float h = 0.0f;
#pragma unroll
    for (int c = 0; c < NCHUNK; c++) {
        size_t i = ((size_t)b * NCHUNK + c) * DI + d;
        Carry[i] = h;
        h = Aprod[i] * h + Hend[i];
    }
}

__global__ void scan_out(const float* __restrict__ xz,
                         const float* __restrict__ xc,
                         const float* __restrict__ dtp,
                         const float* __restrict__ Bp,
                         const float* __restrict__ Cp,
                         const float* __restrict__ bdt,
                         const float* __restrict__ A_log,
                         const float* __restrict__ Carry,
                         float* __restrict__ yt) {
    int idx = blockIdx.x * blockDim.x + threadIdx.x;
    if (idx >= BB * NCHUNK * DI) return;
    int d  = idx % DI;
    int bc = idx / DI;
    int c  = bc % NCHUNK;
    int b  = bc / NCHUNK;

    const float bd = bdt[d];
    const float Ad = -expf(A_log[d]);
    int l0 = c * LCH;
    size_t off  = ((size_t)b * LL + l0) * DI + d;
    size_t zoff = ((size_t)b * LL + l0) * (size_t)(2 * DI) + DI + d;

    float uprev = 0.0f;
    if (l0 > 0) uprev = xc[off - DI] * sig_f(Bp[off - DI]);

    float h = Carry[idx];
    for (int l = 0; l < LCH; l++) {
        float dtv = sp_f(dtp[off] + bd);
        float la  = fminf(fmaxf(Ad * dtv, -10.0f), -0.0001f);
        float a   = __expf(la);
        float u   = xc[off] * sig_f(Bp[off]);
        h = a * h + dtv * 0.5f * (uprev + u);
        uprev = u;

        float Ct = tanhf(Cp[off]);
        float zv = xz[zoff];
        float yv = h * Ct * (zv * sig_f(zv));
        yt[off]  = tf32r(yv);

        off  += DI;
        zoff += 2 * DI;
    }
}

// ---------------------------------------------------------------------------
// Launch
// ---------------------------------------------------------------------------
extern "C" void kernel_launch(void* const* d_in, const int* in_sizes, int n_in,
                              void* d_out, int out_size) {
    const float* x     = (const float*)d_in[0];
    const float* Wi    = (const float*)d_in[1];
    const float* Wconv = (const float*)d_in[2];
    const float* bconv = (const float*)d_in[3];
    const float* Wdt   = (const float*)d_in[4];
    const float* bdt   = (const float*)d_in[5];
    const float* WB    = (const float*)d_in[6];
    const float* WC    = (const float*)d_in[7];
    const float* Wo    = (const float*)d_in[8];
    const float* A_log = (const float*)d_in[9];
    float*       out   = (float*)d_out;

    float *xz, *xc, *xct, *dtp, *Bpp, *Cpp, *yt, *xt;
    float *Wit, *Wdtt, *WBt, *WCt, *Wot, *Aprod, *Hend, *Carry;

    cudaGetSymbolAddress((void**)&xz,   g_xz);
    cudaGetSymbolAddress((void**)&xc,   g_xc);
    cudaGetSymbolAddress((void**)&xct,  g_xct);
    cudaGetSymbolAddress((void**)&dtp,  g_dtp);
    cudaGetSymbolAddress((void**)&Bpp,  g_Bpp);
    cudaGetSymbolAddress((void**)&Cpp,  g_Cpp);
    cudaGetSymbolAddress((void**)&yt,   g_yt);
    cudaGetSymbolAddress((void**)&xt,   g_xt);
    cudaGetSymbolAddress((void**)&Wit,  g_Wit);
    cudaGetSymbolAddress((void**)&Wdtt, g_Wdtt);
    cudaGetSymbolAddress((void**)&WBt,  g_WBt);
    cudaGetSymbolAddress((void**)&WCt,  g_WCt);
    cudaGetSymbolAddress((void**)&Wot,  g_Wot);
    cudaGetSymbolAddress((void**)&Aprod, g_Aprod);
    cudaGetSymbolAddress((void**)&Hend,  g_Hend);
    cudaGetSymbolAddress((void**)&Carry, g_Carry);

    cudaFuncSetAttribute(gemm_tf32, cudaFuncAttributeMaxDynamicSharedMemorySize,
                         GEMM_SMEM);

    const int M = MTOT;

    // 0) tf32 pre-round of GEMM operands
    {
        size_t n;
        n = (size_t)M * DM;
        round_kernel<<<(unsigned)(n / 4 / 256), 256>>>(x, xt, n);
        n = (size_t)2 * DI * DM;
        round_kernel<<<(unsigned)(n / 4 / 256), 256>>>(Wi, Wit, n);
        n = (size_t)DI * DI;
        round_kernel<<<(unsigned)(n / 4 / 256), 256>>>(Wdt, Wdtt, n);
        round_kernel<<<(unsigned)(n / 4 / 256), 256>>>(WB, WBt, n);
        round_kernel<<<(unsigned)(n / 4 / 256), 256>>>(WC, WCt, n);
        n = (size_t)DM * DI;
        round_kernel<<<(unsigned)(n / 4 / 256), 256>>>(Wo, Wot, n);
    }

    // 1) in_proj: xz[M, 4096] = xt @ Wit^T
    gemm_tf32<<<dim3((2 * DI) / BN, M / BM), 256, GEMM_SMEM>>>(xt, Wit, xz, DM, 2 * DI);

    // 2) depthwise causal conv + SiLU
    conv_silu_kernel<<<(unsigned)(((size_t)M * DI) / 256), 256>>>(xz, Wconv, bconv, xc, xct);

    // 3) dt/B/C projections
    gemm_tf32<<<dim3(DI / BN, M / BM), 256, GEMM_SMEM>>>(xct, Wdtt, dtp, DI, DI);
    gemm_tf32<<<dim3(DI / BN, M / BM), 256, GEMM_SMEM>>>(xct, WBt,  Bpp, DI, DI);
    gemm_tf32<<<dim3(DI / BN, M / BM), 256, GEMM_SMEM>>>(xct, WCt,  Cpp, DI, DI);

    // 4) chunked scan (3 passes)
    scan_chunks<<<(BB * NCHUNK * DI) / 256, 256>>>(xc, dtp, Bpp, bdt, A_log, Aprod, Hend);
    scan_carry <<<(BB * DI) / 256, 256>>>(Aprod, Hend, Carry);
    scan_out   <<<(BB * NCHUNK * DI) / 256, 256>>>(xz, xc, dtp, Bpp, Cpp, bdt, A_log,
                                                   Carry, yt);

    // 5) out_proj
    gemm_tf32<<<dim3(DM / BN, M / BM), 256, GEMM_SMEM>>>(yt, Wot, out, DI, DM);
}

// round 10
// speedup vs baseline: 1.6210x; 1.0109x over previous
#include <cuda_runtime.h>
#include <mma.h>
#include <cstdint>

using namespace nvcuda;

#define BB 4
#define LL 4096
#define DM 1024
#define DI 2048
#define MTOT (BB * LL)          // 16384
#define NCHUNK 16
#define LCH (LL / NCHUNK)       // 256

// ---------------------------------------------------------------------------
// Scratch (device globals; allocation is forbidden in kernel_launch)
// ---------------------------------------------------------------------------
__device__ __align__(1024) float g_xz  [(size_t)MTOT * (2 * DI)]; // in_proj out
__device__ __align__(1024) float g_xc  [(size_t)MTOT * DI];       // conv out fp32
__device__ __align__(1024) float g_xct [(size_t)MTOT * DI];       // conv out tf32
__device__ __align__(1024) float g_dtp [(size_t)MTOT * DI];
__device__ __align__(1024) float g_Bpp [(size_t)MTOT * DI];
__device__ __align__(1024) float g_Cpp [(size_t)MTOT * DI];
__device__ __align__(1024) float g_yt  [(size_t)MTOT * DI];       // scan out tf32

__device__ __align__(1024) float g_xt  [(size_t)MTOT * DM];       // x tf32
__device__ __align__(1024) float g_Wit [(size_t)2 * DI * DM];
__device__ __align__(1024) float g_Wdtt[(size_t)DI * DI];
__device__ __align__(1024) float g_WBt [(size_t)DI * DI];
__device__ __align__(1024) float g_WCt [(size_t)DI * DI];
__device__ __align__(1024) float g_Wot [(size_t)DM * DI];

__device__ float g_Aprod[BB * NCHUNK * DI];
__device__ float g_Hend [BB * NCHUNK * DI];
__device__ float g_Carry[BB * NCHUNK * DI];

// ---------------------------------------------------------------------------
// helpers
// ---------------------------------------------------------------------------
__device__ __forceinline__ float tf32r(float v) {
    float r;
    asm("cvt.rna.tf32.f32 %0, %1;" : "=f"(r) : "f"(v));
    return r;
}

__device__ __forceinline__ void cp16(float* dst, const float* src) {
    unsigned s = (unsigned)__cvta_generic_to_shared(dst);
    asm volatile("cp.async.cg.shared.global [%0], [%1], 16;" ::"r"(s), "l"(src));
}

// ---------------------------------------------------------------------------
// GEMM: C[M,N] = A[M,K] * W[N,K]^T  (tf32 HMMA, fp32 accumulate)
//   Inputs pre-rounded to tf32 -> no cvt in the mainloop.
//   128x128x32 tiles, 8 warps (4x2), warp tile 32x64.
//   3-stage cp.async pipeline, <=128 regs, 110.6KB smem -> 2 CTAs/SM.
// ---------------------------------------------------------------------------
#define BM 128
#define BN 128
#define BK 32
#define SST 36
#define NSTG 3
#define STAGEF ((BM + BN) * SST)                        // floats per stage
#define GEMM_SMEM (NSTG * STAGEF * (int)sizeof(float))  // 110592 B

__device__ __forceinline__ void load_stage(float* sbase, const float* A,
                                           const float* W, int kt, int K,
                                           int mBase, int nBase, int tid) {
    const float* Ab = A + (size_t)mBase * K + (size_t)kt * BK;
    const float* Wb = W + (size_t)nBase * K + (size_t)kt * BK;
#pragma unroll
    for (int i = 0; i < 8; i++) {
        int chunk = tid + i * 256;          // 0..2047
        int tile  = chunk >> 10;            // 0: A, 1: W
        int rem   = chunk & 1023;
        int row   = rem >> 3;               // 0..127
        int col   = (rem & 7) << 2;         // 0..28
        const float* src = (tile ? Wb : Ab) + (size_t)row * K + col;
        float* dst = sbase + tile * (BM * SST) + row * SST + col;
        cp16(dst, src);
    }
    asm volatile("cp.async.commit_group;" ::: "memory");
}

__global__ __launch_bounds__(256, 2) void gemm_tf32(const float* __restrict__ A,
                                                    const float* __restrict__ W,
                                                    float* __restrict__ C,
                                                    int K, int N) {
    extern __shared__ float smem[];
    const int tid   = threadIdx.x;
    const int warp  = tid >> 5;
    const int wm    = warp & 3;
    const int wn    = warp >> 2;
    const int mBase = blockIdx.y * BM;
    const int nBase = blockIdx.x * BN;

    wmma::fragment<wmma::accumulator, 16, 16, 8, float> acc[2][4];
#pragma unroll
    for (int i = 0; i < 2; i++)
#pragma unroll
        for (int j = 0; j < 4; j++) wmma::fill_fragment(acc[i][j], 0.0f);

    const int KT = K / BK;

    // prologue: stages 0 and 1 in flight
    load_stage(smem + 0 * STAGEF, A, W, 0, K, mBase, nBase, tid);
    load_stage(smem + 1 * STAGEF, A, W, 1, K, mBase, nBase, tid);

    for (int kt = 0; kt < KT; kt++) {
        // stage kt must be complete; at most the (kt+1) group may stay pending
        if (kt + 1 < KT) asm volatile("cp.async.wait_group 1;" ::: "memory");
        else             asm volatile("cp.async.wait_group 0;" ::: "memory");
        // barrier: (a) makes stage kt visible to all warps, (b) guarantees all
        // warps finished reading stage kt-1 whose slot (kt+2)%3 we now refill
        __syncthreads();

        if (kt + 2 < KT)
            load_stage(smem + ((kt + 2) % NSTG) * STAGEF, A, W, kt + 2, K,
                       mBase, nBase, tid);

        const float* As = smem + (kt % NSTG) * STAGEF;
        const float* Bs = As + BM * SST;

#pragma unroll
        for (int kk = 0; kk < BK / 8; kk++) {
            wmma::fragment<wmma::matrix_a, 16, 16, 8, wmma::precision::tf32,
                           wmma::row_major> af[2];
            wmma::fragment<wmma::matrix_b, 16, 16, 8, wmma::precision::tf32,
                           wmma::col_major> bf[4];
#pragma unroll
            for (int i = 0; i < 2; i++)
                wmma::load_matrix_sync(af[i], As + (wm * 32 + i * 16) * SST + kk * 8, SST);
#pragma unroll
            for (int j = 0; j < 4; j++)
                wmma::load_matrix_sync(bf[j], Bs + (wn * 64 + j * 16) * SST + kk * 8, SST);
#pragma unroll
            for (int i = 0; i < 2; i++)
#pragma unroll
                for (int j = 0; j < 4; j++)
                    wmma::mma_sync(acc[i][j], af[i], bf[j], acc[i][j]);
        }
    }

#pragma unroll
    for (int i = 0; i < 2; i++)
#pragma unroll
        for (int j = 0; j < 4; j++) {
            size_t row = (size_t)(mBase + wm * 32 + i * 16);
            int    col = nBase + wn * 64 + j * 16;
            wmma::store_matrix_sync(C + row * N + col, acc[i][j], N,
                                    wmma::mem_row_major);
        }
}

// ---------------------------------------------------------------------------
// tf32 pre-round (RNA) — producers for GEMM operands
// ---------------------------------------------------------------------------
__global__ void round_kernel(const float* __restrict__ in,
                             float* __restrict__ out, size_t n) {
    size_t i = ((size_t)blockIdx.x * blockDim.x + threadIdx.x) * 4;
    if (i >= n) return;
    float4 v = *(const float4*)(in + i);
    v.x = tf32r(v.x); v.y = tf32r(v.y); v.z = tf32r(v.z); v.w = tf32r(v.w);
    *(float4*)(out + i) = v;
}

// ---------------------------------------------------------------------------
// depthwise causal conv1d (k=4) + bias + SiLU
// ---------------------------------------------------------------------------
__global__ void conv_silu_kernel(const float* __restrict__ xz,
                                 const float* __restrict__ Wc,
                                 const float* __restrict__ bc,
                                 float* __restrict__ xc,
                                 float* __restrict__ xct) {
    size_t idx = (size_t)blockIdx.x * blockDim.x + threadIdx.x;
    if (idx >= (size_t)MTOT * DI) return;
    int d     = (int)(idx % DI);
    size_t bl = idx / DI;
    int l     = (int)(bl % LL);

    const float* xp = xz + bl * (size_t)(2 * DI) + d;
    float acc = bc[d];
#pragma unroll
    for (int j = 0; j < 4; j++) {
        int ll = l - 3 + j;
        if (ll >= 0) acc += Wc[d * 4 + j] * xp[(ptrdiff_t)(j - 3) * (2 * DI)];
    }
    float r = acc * (1.0f / (1.0f + __expf(-acc)));
    xc[idx]  = r;
    xct[idx] = tf32r(r);
}

// ---------------------------------------------------------------------------
// Chunked SSM scan (3 passes); arithmetic identical to the serial recurrence
//   h_t = exp(clip(A*softplus(dtp_t+bdt))) * h_{t-1} + dt_t*0.5*(u_{t-1}+u_t)
// ---------------------------------------------------------------------------
__device__ __forceinline__ float sp_f(float x) {
    return (x > 20.0f) ? x : log1pf(__expf(x));
}
__device__ __forceinline__ float sig_f(float x) { return 1.0f / (1.0f + __expf(-x)); }

__global__ void scan_chunks(const float* __restrict__ xc,
                            const float* __restrict__ dtp,
                            const float* __restrict__ Bp,
                            const float* __restrict__ bdt,
                            const float* __restrict__ A_log,
                            float* __restrict__ Aprod, float* __restrict__ Hend) {
    int idx = blockIdx.x * blockDim.x + threadIdx.x;    // BB*NCHUNK*DI
    if (idx >= BB * NCHUNK * DI) return;
    int d  = idx % DI;
    int bc = idx / DI;
    int c  = bc % NCHUNK;
    int b  = bc / NCHUNK;

    const float bd = bdt[d];
    const float Ad = -expf(A_log[d]);
    int l0 = c * LCH;
    size_t off = ((size_t)b * LL + l0) * DI + d;

    float uprev = 0.0f;
    if (l0 > 0) uprev = xc[off - DI] * sig_f(Bp[off - DI]);

    float h = 0.0f, A = 1.0f;
    for (int l = 0; l < LCH; l++) {
        float dtv = sp_f(dtp[off] + bd);
        float la  = fminf(fmaxf(Ad * dtv, -10.0f), -0.0001f);
        float a   = __expf(la);
        float u   = xc[off] * sig_f(Bp[off]);
        h = a * h + dtv * 0.5f * (uprev + u);
        A *= a;
        uprev = u;
        off += DI;
    }
    Aprod[idx] = A;
    Hend[idx]  = h;
}

__global__ void scan_carry(const float* __restrict__ Aprod,
                           const float* __restrict__ Hend,
                           float* __restrict__ Carry) {
    int t = blockIdx.x * blockDim.x + threadIdx.x;      // BB*DI
    if (t >= BB * DI) return;
    int d = t % DI, b = t / DI;
    float h = 0.0f;
#pragma unroll
    for (int c = 0; c < NCHUNK; c++) {
        size_t i = ((size_t)b * NCHUNK + c) * DI + d;
        Carry[i] = h;
        h = Aprod[i] * h + Hend[i];
    }
}

__global__ void scan_out(const float* __restrict__ xz,
                         const float* __restrict__ xc,
                         const float* __restrict__ dtp,
                         const float* __restrict__ Bp,
                         const float* __restrict__ Cp,
                         const float* __restrict__ bdt,
                         const float* __restrict__ A_log,
                         const float* __restrict__ Carry,
                         float* __restrict__ yt) {
    int idx = blockIdx.x * blockDim.x + threadIdx.x;
    if (idx >= BB * NCHUNK * DI) return;
    int d  = idx % DI;
    int bc = idx / DI;
    int c  = bc % NCHUNK;
    int b  = bc / NCHUNK;

    const float bd = bdt[d];
    const float Ad = -expf(A_log[d]);
    int l0 = c * LCH;
    size_t off  = ((size_t)b * LL + l0) * DI + d;
    size_t zoff = ((size_t)b * LL + l0) * (size_t)(2 * DI) + DI + d;

    float uprev = 0.0f;
    if (l0 > 0) uprev = xc[off - DI] * sig_f(Bp[off - DI]);

    float h = Carry[idx];
    for (int l = 0; l < LCH; l++) {
        float dtv = sp_f(dtp[off] + bd);
        float la  = fminf(fmaxf(Ad * dtv, -10.0f), -0.0001f);
        float a   = __expf(la);
        float u   = xc[off] * sig_f(Bp[off]);
        h = a * h + dtv * 0.5f * (uprev + u);
        uprev = u;

        float Ct = tanhf(Cp[off]);
        float zv = xz[zoff];
        float yv = h * Ct * (zv * sig_f(zv));
        yt[off]  = tf32r(yv);

        off  += DI;
        zoff += 2 * DI;
    }
}

// ---------------------------------------------------------------------------
// Launch
// ---------------------------------------------------------------------------
extern "C" void kernel_launch(void* const* d_in, const int* in_sizes, int n_in,
                              void* d_out, int out_size) {
    const float* x     = (const float*)d_in[0];
    const float* Wi    = (const float*)d_in[1];
    const float* Wconv = (const float*)d_in[2];
    const float* bconv = (const float*)d_in[3];
    const float* Wdt   = (const float*)d_in[4];
    const float* bdt   = (const float*)d_in[5];
    const float* WB    = (const float*)d_in[6];
    const float* WC    = (const float*)d_in[7];
    const float* Wo    = (const float*)d_in[8];
    const float* A_log = (const float*)d_in[9];
    float*       out   = (float*)d_out;

    float *xz, *xc, *xct, *dtp, *Bpp, *Cpp, *yt, *xt;
    float *Wit, *Wdtt, *WBt, *WCt, *Wot, *Aprod, *Hend, *Carry;

    cudaGetSymbolAddress((void**)&xz,   g_xz);
    cudaGetSymbolAddress((void**)&xc,   g_xc);
    cudaGetSymbolAddress((void**)&xct,  g_xct);
    cudaGetSymbolAddress((void**)&dtp,  g_dtp);
    cudaGetSymbolAddress((void**)&Bpp,  g_Bpp);
    cudaGetSymbolAddress((void**)&Cpp,  g_Cpp);
    cudaGetSymbolAddress((void**)&yt,   g_yt);
    cudaGetSymbolAddress((void**)&xt,   g_xt);
    cudaGetSymbolAddress((void**)&Wit,  g_Wit);
    cudaGetSymbolAddress((void**)&Wdtt, g_Wdtt);
    cudaGetSymbolAddress((void**)&WBt,  g_WBt);
    cudaGetSymbolAddress((void**)&WCt,  g_WCt);
    cudaGetSymbolAddress((void**)&Wot,  g_Wot);
    cudaGetSymbolAddress((void**)&Aprod, g_Aprod);
    cudaGetSymbolAddress((void**)&Hend,  g_Hend);
    cudaGetSymbolAddress((void**)&Carry, g_Carry);

    cudaFuncSetAttribute(gemm_tf32, cudaFuncAttributeMaxDynamicSharedMemorySize,
                         GEMM_SMEM);

    const int M = MTOT;

    // 0) tf32 pre-round of GEMM operands
    {
        size_t n;
        n = (size_t)M * DM;
        round_kernel<<<(unsigned)(n / 4 / 256), 256>>>(x, xt, n);
        n = (size_t)2 * DI * DM;
        round_kernel<<<(unsigned)(n / 4 / 256), 256>>>(Wi, Wit, n);
        n = (size_t)DI * DI;
        round_kernel<<<(unsigned)(n / 4 / 256), 256>>>(Wdt, Wdtt, n);
        round_kernel<<<(unsigned)(n / 4 / 256), 256>>>(WB, WBt, n);
        round_kernel<<<(unsigned)(n / 4 / 256), 256>>>(WC, WCt, n);
        n = (size_t)DM * DI;
        round_kernel<<<(unsigned)(n / 4 / 256), 256>>>(Wo, Wot, n);
    }

    // 1) in_proj: xz[M, 4096] = xt @ Wit^T
    gemm_tf32<<<dim3((2 * DI) / BN, M / BM), 256, GEMM_SMEM>>>(xt, Wit, xz, DM, 2 * DI);

    // 2) depthwise causal conv + SiLU
    conv_silu_kernel<<<(unsigned)(((size_t)M * DI) / 256), 256>>>(xz, Wconv, bconv, xc, xct);

    // 3) dt/B/C projections
    gemm_tf32<<<dim3(DI / BN, M / BM), 256, GEMM_SMEM>>>(xct, Wdtt, dtp, DI, DI);
    gemm_tf32<<<dim3(DI / BN, M / BM), 256, GEMM_SMEM>>>(xct, WBt,  Bpp, DI, DI);
    gemm_tf32<<<dim3(DI / BN, M / BM), 256, GEMM_SMEM>>>(xct, WCt,  Cpp, DI, DI);

    // 4) chunked scan (3 passes)
    scan_chunks<<<(BB * NCHUNK * DI) / 256, 256>>>(xc, dtp, Bpp, bdt, A_log, Aprod, Hend);
    scan_carry <<<(BB * DI) / 256, 256>>>(Aprod, Hend, Carry);
    scan_out   <<<(BB * NCHUNK * DI) / 256, 256>>>(xz, xc, dtp, Bpp, Cpp, bdt, A_log,
                                                   Carry, yt);

    // 5) out_proj
    gemm_tf32<<<dim3(DM / BN, M / BM), 256, GEMM_SMEM>>>(yt, Wot, out, DI, DM);
}

// round 11
// speedup vs baseline: 1.8332x; 1.1309x over previous
#include <cuda_runtime.h>
#include <mma.h>
#include <cstdint>

using namespace nvcuda;

#define BB 4
#define LL 4096
#define DM 1024
#define DI 2048
#define MTOT (BB * LL)          // 16384
#define NCHUNK 16
#define LCH (LL / NCHUNK)       // 256

// ---------------------------------------------------------------------------
// Scratch (device globals; allocation is forbidden in kernel_launch)
// ---------------------------------------------------------------------------
__device__ __align__(1024) float g_xz  [(size_t)MTOT * (2 * DI)]; // in_proj out
__device__ __align__(1024) float g_xc  [(size_t)MTOT * DI];       // conv out fp32
__device__ __align__(1024) float g_xct [(size_t)MTOT * DI];       // conv out tf32
__device__ __align__(1024) float g_dtp [(size_t)MTOT * DI];
__device__ __align__(1024) float g_Bpp [(size_t)MTOT * DI];
__device__ __align__(1024) float g_Cpp [(size_t)MTOT * DI];
__device__ __align__(1024) float g_yt  [(size_t)MTOT * DI];       // scan out tf32

__device__ __align__(1024) float g_xt  [(size_t)MTOT * DM];       // x tf32
__device__ __align__(1024) float g_Wit [(size_t)2 * DI * DM];
__device__ __align__(1024) float g_Wdtt[(size_t)DI * DI];
__device__ __align__(1024) float g_WBt [(size_t)DI * DI];
__device__ __align__(1024) float g_WCt [(size_t)DI * DI];
__device__ __align__(1024) float g_Wot [(size_t)DM * DI];

__device__ float g_Aprod[BB * NCHUNK * DI];
__device__ float g_Hend [BB * NCHUNK * DI];
__device__ float g_Carry[BB * NCHUNK * DI];

// ---------------------------------------------------------------------------
// helpers
// ---------------------------------------------------------------------------
__device__ __forceinline__ float tf32r(float v) {
    float r;
    asm("cvt.rna.tf32.f32 %0, %1;" : "=f"(r) : "f"(v));
    return r;
}

__device__ __forceinline__ void cp16(float* dst, const float* src) {
    unsigned s = (unsigned)__cvta_generic_to_shared(dst);
    asm volatile("cp.async.cg.shared.global [%0], [%1], 16;" ::"r"(s), "l"(src));
}

// ---------------------------------------------------------------------------
// GEMM: C[M,N] = A[M,K] * W[N,K]^T  (tf32 HMMA, fp32 accumulate)
//   Inputs pre-rounded to tf32 -> no cvt in the mainloop.
//   128x128x32 block, 4 warps (2x2), warp tile 64x64 (16 wmma frags).
//   3-stage cp.async pipeline, 110.6KB smem -> 2 CTAs/SM (8 warps/SM).
//   Rationale: 64x64 warp tiles cut smem crossbar reads from 96KB to 64KB
//   per block k-iter (the measured bottleneck) at identical HMMA count.
// ---------------------------------------------------------------------------
#define BM 128
#define BN 128
#define BK 32
#define SST 36
#define NSTG 3
#define NTHR 128
#define STAGEF ((BM + BN) * SST)                        // floats per stage
#define GEMM_SMEM (NSTG * STAGEF * (int)sizeof(float))  // 110592 B

__device__ __forceinline__ void load_stage(float* sbase, const float* A,
                                           const float* W, int kt, int K,
                                           int mBase, int nBase, int tid) {
    const float* Ab = A + (size_t)mBase * K + (size_t)kt * BK;
    const float* Wb = W + (size_t)nBase * K + (size_t)kt * BK;
#pragma unroll
    for (int i = 0; i < 16; i++) {
        int chunk = tid + i * NTHR;         // 0..2047
        int tile  = chunk >> 10;            // 0: A, 1: W
        int rem   = chunk & 1023;
        int row   = rem >> 3;               // 0..127
        int col   = (rem & 7) << 2;         // 0..28
        const float* src = (tile ? Wb : Ab) + (size_t)row * K + col;
        float* dst = sbase + tile * (BM * SST) + row * SST + col;
        cp16(dst, src);
    }
    asm volatile("cp.async.commit_group;" ::: "memory");
}

__global__ __launch_bounds__(NTHR, 2) void gemm_tf32(const float* __restrict__ A,
                                                     const float* __restrict__ W,
                                                     float* __restrict__ C,
                                                     int K, int N) {
    extern __shared__ float smem[];
    const int tid   = threadIdx.x;
    const int warp  = tid >> 5;
    const int wm    = warp & 1;             // 2 warp rows  -> 64 M each
    const int wn    = warp >> 1;            // 2 warp cols  -> 64 N each
    const int mBase = blockIdx.y * BM;
    const int nBase = blockIdx.x * BN;

    wmma::fragment<wmma::accumulator, 16, 16, 8, float> acc[4][4];
#pragma unroll
    for (int i = 0; i < 4; i++)
#pragma unroll
        for (int j = 0; j < 4; j++) wmma::fill_fragment(acc[i][j], 0.0f);

    const int KT = K / BK;

    // prologue: stages 0 and 1 in flight
    load_stage(smem + 0 * STAGEF, A, W, 0, K, mBase, nBase, tid);
    load_stage(smem + 1 * STAGEF, A, W, 1, K, mBase, nBase, tid);

    for (int kt = 0; kt < KT; kt++) {
        // stage kt must be complete; at most the (kt+1) group may stay pending
        if (kt + 1 < KT) asm volatile("cp.async.wait_group 1;" ::: "memory");
        else             asm volatile("cp.async.wait_group 0;" ::: "memory");
        // barrier: (a) stage kt visible to all warps, (b) all warps done
        // reading stage kt-1 whose slot (kt+2)%3 we refill below
        __syncthreads();

        if (kt + 2 < KT)
            load_stage(smem + ((kt + 2) % NSTG) * STAGEF, A, W, kt + 2, K,
                       mBase, nBase, tid);

        const float* As = smem + (kt % NSTG) * STAGEF;
        const float* Bs = As + BM * SST;

#pragma unroll
        for (int kk = 0; kk < BK / 8; kk++) {
            wmma::fragment<wmma::matrix_a, 16, 16, 8, wmma::precision::tf32,
                           wmma::row_major> af[4];
            wmma::fragment<wmma::matrix_b, 16, 16, 8, wmma::precision::tf32,
                           wmma::col_major> bf[4];
#pragma unroll
            for (int i = 0; i < 4; i++)
                wmma::load_matrix_sync(af[i], As + (wm * 64 + i * 16) * SST + kk * 8, SST);
#pragma unroll
            for (int j = 0; j < 4; j++)
                wmma::load_matrix_sync(bf[j], Bs + (wn * 64 + j * 16) * SST + kk * 8, SST);
#pragma unroll
            for (int i = 0; i < 4; i++)
#pragma unroll
                for (int j = 0; j < 4; j++)
                    wmma::mma_sync(acc[i][j], af[i], bf[j], acc[i][j]);
        }
    }

#pragma unroll
    for (int i = 0; i < 4; i++)
#pragma unroll
        for (int j = 0; j < 4; j++) {
            size_t row = (size_t)(mBase + wm * 64 + i * 16);
            int    col = nBase + wn * 64 + j * 16;
            wmma::store_matrix_sync(C + row * N + col, acc[i][j], N,
                                    wmma::mem_row_major);
        }
}

// ---------------------------------------------------------------------------
// tf32 pre-round (RNA) — producers for GEMM operands
// ---------------------------------------------------------------------------
__global__ void round_kernel(const float* __restrict__ in,
                             float* __restrict__ out, size_t n) {
    size_t i = ((size_t)blockIdx.x * blockDim.x + threadIdx.x) * 4;
    if (i >= n) return;
    float4 v = *(const float4*)(in + i);
    v.x = tf32r(v.x); v.y = tf32r(v.y); v.z = tf32r(v.z); v.w = tf32r(v.w);
    *(float4*)(out + i) = v;
}

// ---------------------------------------------------------------------------
// depthwise causal conv1d (k=4) + bias + SiLU
// ---------------------------------------------------------------------------
__global__ void conv_silu_kernel(const float* __restrict__ xz,
                                 const float* __restrict__ Wc,
                                 const float* __restrict__ bc,
                                 float* __restrict__ xc,
                                 float* __restrict__ xct) {
    size_t idx = (size_t)blockIdx.x * blockDim.x + threadIdx.x;
    if (idx >= (size_t)MTOT * DI) return;
    int d     = (int)(idx % DI);
    size_t bl = idx / DI;
    int l     = (int)(bl % LL);

    const float* xp = xz + bl * (size_t)(2 * DI) + d;
    float acc = bc[d];
#pragma unroll
    for (int j = 0; j < 4; j++) {
        int ll = l - 3 + j;
        if (ll >= 0) acc += Wc[d * 4 + j] * xp[(ptrdiff_t)(j - 3) * (2 * DI)];
    }
    float r = acc * (1.0f / (1.0f + __expf(-acc)));
    xc[idx]  = r;
    xct[idx] = tf32r(r);
}

// ---------------------------------------------------------------------------
// Chunked SSM scan (3 passes); arithmetic identical to the serial recurrence
//   h_t = exp(clip(A*softplus(dtp_t+bdt))) * h_{t-1} + dt_t*0.5*(u_{t-1}+u_t)
// ---------------------------------------------------------------------------
__device__ __forceinline__ float sp_f(float x) {
    return (x > 20.0f) ? x : log1pf(__expf(x));
}
__device__ __forceinline__ float sig_f(float x) { return 1.0f / (1.0f + __expf(-x)); }

__global__ void scan_chunks(const float* __restrict__ xc,
                            const float* __restrict__ dtp,
                            const float* __restrict__ Bp,
                            const float* __restrict__ bdt,
                            const float* __restrict__ A_log,
                            float* __restrict__ Aprod, float* __restrict__ Hend) {
    int idx = blockIdx.x * blockDim.x + threadIdx.x;    // BB*NCHUNK*DI
    if (idx >= BB * NCHUNK * DI) return;
    int d  = idx % DI;
    int bc = idx / DI;
    int c  = bc % NCHUNK;
    int b  = bc / NCHUNK;

    const float bd = bdt[d];
    const float Ad = -expf(A_log[d]);
    int l0 = c * LCH;
    size_t off = ((size_t)b * LL + l0) * DI + d;

    float uprev = 0.0f;
    if (l0 > 0) uprev = xc[off - DI] * sig_f(Bp[off - DI]);

    float h = 0.0f, A = 1.0f;
    for (int l = 0; l < LCH; l++) {
        float dtv = sp_f(dtp[off] + bd);
        float la  = fminf(fmaxf(Ad * dtv, -10.0f), -0.0001f);
        float a   = __expf(la);
        float u   = xc[off] * sig_f(Bp[off]);
        h = a * h + dtv * 0.5f * (uprev + u);
        A *= a;
        uprev = u;
        off += DI;
    }
    Aprod[idx] = A;
    Hend[idx]  = h;
}

__global__ void scan_carry(const float* __restrict__ Aprod,
                           const float* __restrict__ Hend,
                           float* __restrict__ Carry) {
    int t = blockIdx.x * blockDim.x + threadIdx.x;      // BB*DI
    if (t >= BB * DI) return;
    int d = t % DI, b = t / DI;
    float h = 0.0f;
#pragma unroll
    for (int c = 0; c < NCHUNK; c++) {
        size_t i = ((size_t)b * NCHUNK + c) * DI + d;
        Carry[i] = h;
        h = Aprod[i] * h + Hend[i];
    }
}

__global__ void scan_out(const float* __restrict__ xz,
                         const float* __restrict__ xc,
                         const float* __restrict__ dtp,
                         const float* __restrict__ Bp,
                         const float* __restrict__ Cp,
                         const float* __restrict__ bdt,
                         const float* __restrict__ A_log,
                         const float* __restrict__ Carry,
                         float* __restrict__ yt) {
    int idx = blockIdx.x * blockDim.x + threadIdx.x;
    if (idx >= BB * NCHUNK * DI) return;
    int d  = idx % DI;
    int bc = idx / DI;
    int c  = bc % NCHUNK;
    int b  = bc / NCHUNK;

    const float bd = bdt[d];
    const float Ad = -expf(A_log[d]);
    int l0 = c * LCH;
    size_t off  = ((size_t)b * LL + l0) * DI + d;
    size_t zoff = ((size_t)b * LL + l0) * (size_t)(2 * DI) + DI + d;

    float uprev = 0.0f;
    if (l0 > 0) uprev = xc[off - DI] * sig_f(Bp[off - DI]);

    float h = Carry[idx];
    for (int l = 0; l < LCH; l++) {
        float dtv = sp_f(dtp[off] + bd);
        float la  = fminf(fmaxf(Ad * dtv, -10.0f), -0.0001f);
        float a   = __expf(la);
        float u   = xc[off] * sig_f(Bp[off]);
        h = a * h + dtv * 0.5f * (uprev + u);
        uprev = u;

        float Ct = tanhf(Cp[off]);
        float zv = xz[zoff];
        float yv = h * Ct * (zv * sig_f(zv));
        yt[off]  = tf32r(yv);

        off  += DI;
        zoff += 2 * DI;
    }
}

// ---------------------------------------------------------------------------
// Launch
// ---------------------------------------------------------------------------
extern "C" void kernel_launch(void* const* d_in, const int* in_sizes, int n_in,
                              void* d_out, int out_size) {
    const float* x     = (const float*)d_in[0];
    const float* Wi    = (const float*)d_in[1];
    const float* Wconv = (const float*)d_in[2];
    const float* bconv = (const float*)d_in[3];
    const float* Wdt   = (const float*)d_in[4];
    const float* bdt   = (const float*)d_in[5];
    const float* WB    = (const float*)d_in[6];
    const float* WC    = (const float*)d_in[7];
    const float* Wo    = (const float*)d_in[8];
    const float* A_log = (const float*)d_in[9];
    float*       out   = (float*)d_out;

    float *xz, *xc, *xct, *dtp, *Bpp, *Cpp, *yt, *xt;
    float *Wit, *Wdtt, *WBt, *WCt, *Wot, *Aprod, *Hend, *Carry;

    cudaGetSymbolAddress((void**)&xz,   g_xz);
    cudaGetSymbolAddress((void**)&xc,   g_xc);
    cudaGetSymbolAddress((void**)&xct,  g_xct);
    cudaGetSymbolAddress((void**)&dtp,  g_dtp);
    cudaGetSymbolAddress((void**)&Bpp,  g_Bpp);
    cudaGetSymbolAddress((void**)&Cpp,  g_Cpp);
    cudaGetSymbolAddress((void**)&yt,   g_yt);
    cudaGetSymbolAddress((void**)&xt,   g_xt);
    cudaGetSymbolAddress((void**)&Wit,  g_Wit);
    cudaGetSymbolAddress((void**)&Wdtt, g_Wdtt);
    cudaGetSymbolAddress((void**)&WBt,  g_WBt);
    cudaGetSymbolAddress((void**)&WCt,  g_WCt);
    cudaGetSymbolAddress((void**)&Wot,  g_Wot);
    cudaGetSymbolAddress((void**)&Aprod, g_Aprod);
    cudaGetSymbolAddress((void**)&Hend,  g_Hend);
    cudaGetSymbolAddress((void**)&Carry, g_Carry);

    cudaFuncSetAttribute(gemm_tf32, cudaFuncAttributeMaxDynamicSharedMemorySize,
                         GEMM_SMEM);

    const int M = MTOT;

    // 0) tf32 pre-round of GEMM operands
    {
        size_t n;
        n = (size_t)M * DM;
        round_kernel<<<(unsigned)(n / 4 / 256), 256>>>(x, xt, n);
        n = (size_t)2 * DI * DM;
        round_kernel<<<(unsigned)(n / 4 / 256), 256>>>(Wi, Wit, n);
        n = (size_t)DI * DI;
        round_kernel<<<(unsigned)(n / 4 / 256), 256>>>(Wdt, Wdtt, n);
        round_kernel<<<(unsigned)(n / 4 / 256), 256>>>(WB, WBt, n);
        round_kernel<<<(unsigned)(n / 4 / 256), 256>>>(WC, WCt, n);
        n = (size_t)DM * DI;
        round_kernel<<<(unsigned)(n / 4 / 256), 256>>>(Wo, Wot, n);
    }

    // 1) in_proj: xz[M, 4096] = xt @ Wit^T
    gemm_tf32<<<dim3((2 * DI) / BN, M / BM), NTHR, GEMM_SMEM>>>(xt, Wit, xz, DM, 2 * DI);

    // 2) depthwise causal conv + SiLU
    conv_silu_kernel<<<(unsigned)(((size_t)M * DI) / 256), 256>>>(xz, Wconv, bconv, xc, xct);

    // 3) dt/B/C projections
    gemm_tf32<<<dim3(DI / BN, M / BM), NTHR, GEMM_SMEM>>>(xct, Wdtt, dtp, DI, DI);
    gemm_tf32<<<dim3(DI / BN, M / BM), NTHR, GEMM_SMEM>>>(xct, WBt,  Bpp, DI, DI);
    gemm_tf32<<<dim3(DI / BN, M / BM), NTHR, GEMM_SMEM>>>(xct, WCt,  Cpp, DI, DI);

    // 4) chunked scan (3 passes)
    scan_chunks<<<(BB * NCHUNK * DI) / 256, 256>>>(xc, dtp, Bpp, bdt, A_log, Aprod, Hend);
    scan_carry <<<(BB * DI) / 256, 256>>>(Aprod, Hend, Carry);
    scan_out   <<<(BB * NCHUNK * DI) / 256, 256>>>(xz, xc, dtp, Bpp, Cpp, bdt, A_log,
                                                   Carry, yt);

    // 5) out_proj
    gemm_tf32<<<dim3(DM / BN, M / BM), NTHR, GEMM_SMEM>>>(yt, Wot, out, DI, DM);
}

// round 12
// speedup vs baseline: 6.0341x; 3.2916x over previous
#include <cuda_runtime.h>
#include <cuda_fp16.h>
#include <mma.h>
#include <cstdint>

using namespace nvcuda;

#define BB 4
#define LL 4096
#define DM 1024
#define DI 2048
#define MTOT (BB * LL)          // 16384
#define NCHUNK 16
#define LCH (LL / NCHUNK)       // 256

// ---------------------------------------------------------------------------
// Scratch (device globals; allocation is forbidden in kernel_launch)
// ---------------------------------------------------------------------------
__device__ __align__(1024) float g_xz  [(size_t)MTOT * (2 * DI)]; // in_proj out
__device__ __align__(1024) float g_xc  [(size_t)MTOT * DI];       // conv out fp32
__device__ __align__(1024) float g_dtp [(size_t)MTOT * DI];
__device__ __align__(1024) float g_Bpp [(size_t)MTOT * DI];
__device__ __align__(1024) float g_Cpp [(size_t)MTOT * DI];

__device__ __align__(1024) __half g_xch[(size_t)MTOT * DI];       // conv out fp16
__device__ __align__(1024) __half g_yh [(size_t)MTOT * DI];       // scan out fp16
__device__ __align__(1024) __half g_xh [(size_t)MTOT * DM];       // x fp16
__device__ __align__(1024) __half g_Wih [(size_t)2 * DI * DM];
__device__ __align__(1024) __half g_Wdth[(size_t)DI * DI];
__device__ __align__(1024) __half g_WBh [(size_t)DI * DI];
__device__ __align__(1024) __half g_WCh [(size_t)DI * DI];
__device__ __align__(1024) __half g_Woh [(size_t)DM * DI];

__device__ float g_Aprod[BB * NCHUNK * DI];
__device__ float g_Hend [BB * NCHUNK * DI];
__device__ float g_Carry[BB * NCHUNK * DI];

// ---------------------------------------------------------------------------
// helpers
// ---------------------------------------------------------------------------
__device__ __forceinline__ void cp16h(__half* dst, const __half* src) {
    unsigned s = (unsigned)__cvta_generic_to_shared(dst);
    asm volatile("cp.async.cg.shared.global [%0], [%1], 16;" ::"r"(s), "l"(src));
}

// ---------------------------------------------------------------------------
// GEMM: C[M,N] = A[M,K] * W[N,K]^T  (fp16 HMMA m16n16k16, fp32 accumulate)
//   128x128x32 block, 4 warps (2x2), warp tile 64x64 (16 wmma frags).
//   4-stage cp.async pipeline, 80KB smem -> 2 CTAs/SM.
//   SSTH=40 halfs (80B pitch): ldmatrix row addrs hit banks {20r mod 32},
//   all distinct -> conflict-free fragment loads.
// ---------------------------------------------------------------------------
#define BM 128
#define BN 128
#define BK 32
#define SSTH 40
#define NSTG 4
#define NTHR 128
#define STAGEH ((BM + BN) * SSTH)                        // halfs per stage
#define GEMM_SMEM (NSTG * STAGEH * (int)sizeof(__half))  // 81920 B

__device__ __forceinline__ void load_stage(__half* sbase, const __half* A,
                                           const __half* W, int kt, int K,
                                           int mBase, int nBase, int tid) {
    const __half* Ab = A + (size_t)mBase * K + (size_t)kt * BK;
    const __half* Wb = W + (size_t)nBase * K + (size_t)kt * BK;
    // (128+128) rows x 32 halfs(64B) = 1024 chunks of 16B; 128 thr -> 8 each
#pragma unroll
    for (int i = 0; i < 8; i++) {
        int chunk = tid + i * NTHR;         // 0..1023
        int tile  = chunk >> 9;             // 0: A, 1: W
        int rem   = chunk & 511;
        int row   = rem >> 2;               // 0..127
        int col   = (rem & 3) << 3;         // 0,8,16,24 (halfs)
        const __half* src = (tile ? Wb : Ab) + (size_t)row * K + col;
        __half* dst = sbase + tile * (BM * SSTH) + row * SSTH + col;
        cp16h(dst, src);
    }
    asm volatile("cp.async.commit_group;" ::: "memory");
}

__global__ __launch_bounds__(NTHR, 2) void gemm_fp16(const __half* __restrict__ A,
                                                     const __half* __restrict__ W,
                                                     float* __restrict__ C,
                                                     int K, int N) {
    extern __shared__ __half smem[];
    const int tid   = threadIdx.x;
    const int warp  = tid >> 5;
    const int wm    = warp & 1;             // 2 warp rows -> 64 M each
    const int wn    = warp >> 1;            // 2 warp cols -> 64 N each
    const int mBase = blockIdx.y * BM;
    const int nBase = blockIdx.x * BN;

    wmma::fragment<wmma::accumulator, 16, 16, 16, float> acc[4][4];
#pragma unroll
    for (int i = 0; i < 4; i++)
#pragma unroll
        for (int j = 0; j < 4; j++) wmma::fill_fragment(acc[i][j], 0.0f);

    const int KT = K / BK;

    // prologue: stages 0..2 in flight
    load_stage(smem + 0 * STAGEH, A, W, 0, K, mBase, nBase, tid);
    load_stage(smem + 1 * STAGEH, A, W, 1, K, mBase, nBase, tid);
    load_stage(smem + 2 * STAGEH, A, W, 2, K, mBase, nBase, tid);

    for (int kt = 0; kt < KT; kt++) {
        int rem = KT - 1 - kt;              // stages beyond kt possibly in flight
        if (rem >= 2)      asm volatile("cp.async.wait_group 2;" ::: "memory");
        else if (rem == 1) asm volatile("cp.async.wait_group 1;" ::: "memory");
        else               asm volatile("cp.async.wait_group 0;" ::: "memory");
        // barrier: stage kt visible to all warps; all warps done reading stage
        // kt-1, whose slot (kt+3)%4 is refilled below
        __syncthreads();

        if (kt + 3 < KT)
            load_stage(smem + ((kt + 3) & 3) * STAGEH, A, W, kt + 3, K,
                       mBase, nBase, tid);

        const __half* As = smem + (kt & 3) * STAGEH;
        const __half* Bs = As + BM * SSTH;

#pragma unroll
        for (int kk = 0; kk < BK / 16; kk++) {
            wmma::fragment<wmma::matrix_a, 16, 16, 16, half, wmma::row_major> af[4];
            wmma::fragment<wmma::matrix_b, 16, 16, 16, half, wmma::col_major> bf[4];
#pragma unroll
            for (int i = 0; i < 4; i++)
                wmma::load_matrix_sync(af[i], As + (wm * 64 + i * 16) * SSTH + kk * 16, SSTH);
#pragma unroll
            for (int j = 0; j < 4; j++)
                wmma::load_matrix_sync(bf[j], Bs + (wn * 64 + j * 16) * SSTH + kk * 16, SSTH);
#pragma unroll
            for (int i = 0; i < 4; i++)
#pragma unroll
                for (int j = 0; j < 4; j++)
                    wmma::mma_sync(acc[i][j], af[i], bf[j], acc[i][j]);
        }
    }

#pragma unroll
    for (int i = 0; i < 4; i++)
#pragma unroll
        for (int j = 0; j < 4; j++) {
            size_t row = (size_t)(mBase + wm * 64 + i * 16);
            int    col = nBase + wn * 64 + j * 16;
            wmma::store_matrix_sync(C + row * N + col, acc[i][j], N,
                                    wmma::mem_row_major);
        }
}

// ---------------------------------------------------------------------------
// fp32 -> fp16 producer (8 elements per thread, 16B stores)
// ---------------------------------------------------------------------------
__global__ void to_half_kernel(const float* __restrict__ in,
                               __half* __restrict__ out, size_t n) {
    size_t i = ((size_t)blockIdx.x * blockDim.x + threadIdx.x) * 8;
    if (i >= n) return;
    float4 a = *(const float4*)(in + i);
    float4 b = *(const float4*)(in + i + 4);
    __half2 h[4];
    h[0] = __floats2half2_rn(a.x, a.y);
    h[1] = __floats2half2_rn(a.z, a.w);
    h[2] = __floats2half2_rn(b.x, b.y);
    h[3] = __floats2half2_rn(b.z, b.w);
    *(uint4*)(out + i) = *(uint4*)h;
}

// ---------------------------------------------------------------------------
// depthwise causal conv1d (k=4) + bias + SiLU -> fp32 (scan) + fp16 (GEMM)
// ---------------------------------------------------------------------------
__global__ void conv_silu_kernel(const float* __restrict__ xz,
                                 const float* __restrict__ Wc,
                                 const float* __restrict__ bc,
                                 float* __restrict__ xc,
                                 __half* __restrict__ xch) {
    size_t idx = (size_t)blockIdx.x * blockDim.x + threadIdx.x;
    if (idx >= (size_t)MTOT * DI) return;
    int d     = (int)(idx % DI);
    size_t bl = idx / DI;
    int l     = (int)(bl % LL);

    const float* xp = xz + bl * (size_t)(2 * DI) + d;
    float acc = bc[d];
#pragma unroll
    for (int j = 0; j < 4; j++) {
        int ll = l - 3 + j;
        if (ll >= 0) acc += Wc[d * 4 + j] * xp[(ptrdiff_t)(j - 3) * (2 * DI)];
    }
    float r = acc * (1.0f / (1.0f + __expf(-acc)));
    xc[idx]  = r;
    xch[idx] = __float2half_rn(r);
}

// ---------------------------------------------------------------------------
// Chunked SSM scan (3 passes); arithmetic identical to the serial recurrence
//   h_t = exp(clip(A*softplus(dtp_t+bdt))) * h_{t-1} + dt_t*0.5*(u_{t-1}+u_t)
// ---------------------------------------------------------------------------
__device__ __forceinline__ float sp_f(float x) {
    return (x > 20.0f) ? x : log1pf(__expf(x));
}
__device__ __forceinline__ float sig_f(float x) { return 1.0f / (1.0f + __expf(-x)); }

__global__ void scan_chunks(const float* __restrict__ xc,
                            const float* __restrict__ dtp,
                            const float* __restrict__ Bp,
                            const float* __restrict__ bdt,
                            const float* __restrict__ A_log,
                            float* __restrict__ Aprod, float* __restrict__ Hend) {
    int idx = blockIdx.x * blockDim.x + threadIdx.x;    // BB*NCHUNK*DI
    if (idx >= BB * NCHUNK * DI) return;
    int d  = idx % DI;
    int bc = idx / DI;
    int c  = bc % NCHUNK;
    int b  = bc / NCHUNK;

    const float bd = bdt[d];
    const float Ad = -expf(A_log[d]);
    int l0 = c * LCH;
    size_t off = ((size_t)b * LL + l0) * DI + d;

    float uprev = 0.0f;
    if (l0 > 0) uprev = xc[off - DI] * sig_f(Bp[off - DI]);

    float h = 0.0f, A = 1.0f;
    for (int l = 0; l < LCH; l++) {
        float dtv = sp_f(dtp[off] + bd);
        float la  = fminf(fmaxf(Ad * dtv, -10.0f), -0.0001f);
        float a   = __expf(la);
        float u   = xc[off] * sig_f(Bp[off]);
        h = a * h + dtv * 0.5f * (uprev + u);
        A *= a;
        uprev = u;
        off += DI;
    }
    Aprod[idx] = A;
    Hend[idx]  = h;
}

__global__ void scan_carry(const float* __restrict__ Aprod,
                           const float* __restrict__ Hend,
                           float* __restrict__ Carry) {
    int t = blockIdx.x * blockDim.x + threadIdx.x;      // BB*DI
    if (t >= BB * DI) return;
    int d = t % DI, b = t / DI;
    float h = 0.0f;
#pragma unroll
    for (int c = 0; c < NCHUNK; c++) {
        size_t i = ((size_t)b * NCHUNK + c) * DI + d;
        Carry[i] = h;
        h = Aprod[i] * h + Hend[i];
    }
}

__global__ void scan_out(const float* __restrict__ xz,
                         const float* __restrict__ xc,
                         const float* __restrict__ dtp,
                         const float* __restrict__ Bp,
                         const float* __restrict__ Cp,
                         const float* __restrict__ bdt,
                         const float* __restrict__ A_log,
                         const float* __restrict__ Carry,
                         __half* __restrict__ yh) {
    int idx = blockIdx.x * blockDim.x + threadIdx.x;
    if (idx >= BB * NCHUNK * DI) return;
    int d  = idx % DI;
    int bc = idx / DI;
    int c  = bc % NCHUNK;
    int b  = bc / NCHUNK;

    const float bd = bdt[d];
    const float Ad = -expf(A_log[d]);
    int l0 = c * LCH;
    size_t off  = ((size_t)b * LL + l0) * DI + d;
    size_t zoff = ((size_t)b * LL + l0) * (size_t)(2 * DI) + DI + d;

    float uprev = 0.0f;
    if (l0 > 0) uprev = xc[off - DI] * sig_f(Bp[off - DI]);

    float h = Carry[idx];
    for (int l = 0; l < LCH; l++) {
        float dtv = sp_f(dtp[off] + bd);
        float la  = fminf(fmaxf(Ad * dtv, -10.0f), -0.0001f);
        float a   = __expf(la);
        float u   = xc[off] * sig_f(Bp[off]);
        h = a * h + dtv * 0.5f * (uprev + u);
        uprev = u;

        float Ct = tanhf(Cp[off]);
        float zv = xz[zoff];
        float yv = h * Ct * (zv * sig_f(zv));
        yh[off]  = __float2half_rn(yv);

        off  += DI;
        zoff += 2 * DI;
    }
}

// ---------------------------------------------------------------------------
// Launch
// ---------------------------------------------------------------------------
extern "C" void kernel_launch(void* const* d_in, const int* in_sizes, int n_in,
                              void* d_out, int out_size) {
    const float* x     = (const float*)d_in[0];
    const float* Wi    = (const float*)d_in[1];
    const float* Wconv = (const float*)d_in[2];
    const float* bconv = (const float*)d_in[3];
    const float* Wdt   = (const float*)d_in[4];
    const float* bdt   = (const float*)d_in[5];
    const float* WB    = (const float*)d_in[6];
    const float* WC    = (const float*)d_in[7];
    const float* Wo    = (const float*)d_in[8];
    const float* A_log = (const float*)d_in[9];
    float*       out   = (float*)d_out;

    float *xz, *xc, *dtp, *Bpp, *Cpp, *Aprod, *Hend, *Carry;
    __half *xh, *xch, *yh, *Wih, *Wdth, *WBh, *WCh, *Woh;

    cudaGetSymbolAddress((void**)&xz,   g_xz);
    cudaGetSymbolAddress((void**)&xc,   g_xc);
    cudaGetSymbolAddress((void**)&dtp,  g_dtp);
    cudaGetSymbolAddress((void**)&Bpp,  g_Bpp);
    cudaGetSymbolAddress((void**)&Cpp,  g_Cpp);
    cudaGetSymbolAddress((void**)&xh,   g_xh);
    cudaGetSymbolAddress((void**)&xch,  g_xch);
    cudaGetSymbolAddress((void**)&yh,   g_yh);
    cudaGetSymbolAddress((void**)&Wih,  g_Wih);
    cudaGetSymbolAddress((void**)&Wdth, g_Wdth);
    cudaGetSymbolAddress((void**)&WBh,  g_WBh);
    cudaGetSymbolAddress((void**)&WCh,  g_WCh);
    cudaGetSymbolAddress((void**)&Woh,  g_Woh);
    cudaGetSymbolAddress((void**)&Aprod, g_Aprod);
    cudaGetSymbolAddress((void**)&Hend,  g_Hend);
    cudaGetSymbolAddress((void**)&Carry, g_Carry);

    cudaFuncSetAttribute(gemm_fp16, cudaFuncAttributeMaxDynamicSharedMemorySize,
                         GEMM_SMEM);

    const int M = MTOT;

    // 0) fp16 conversion of GEMM operands
    {
        size_t n;
        n = (size_t)M * DM;
        to_half_kernel<<<(unsigned)(n / 8 / 256), 256>>>(x, xh, n);
        n = (size_t)2 * DI * DM;
        to_half_kernel<<<(unsigned)(n / 8 / 256), 256>>>(Wi, Wih, n);
        n = (size_t)DI * DI;
        to_half_kernel<<<(unsigned)(n / 8 / 256), 256>>>(Wdt, Wdth, n);
        to_half_kernel<<<(unsigned)(n / 8 / 256), 256>>>(WB, WBh, n);
        to_half_kernel<<<(unsigned)(n / 8 / 256), 256>>>(WC, WCh, n);
        n = (size_t)DM * DI;
        to_half_kernel<<<(unsigned)(n / 8 / 256), 256>>>(Wo, Woh, n);
    }

    // 1) in_proj: xz[M, 4096] = xh @ Wih^T
    gemm_fp16<<<dim3((2 * DI) / BN, M / BM), NTHR, GEMM_SMEM>>>(xh, Wih, xz, DM, 2 * DI);

    // 2) depthwise causal conv + SiLU
    conv_silu_kernel<<<(unsigned)(((size_t)M * DI) / 256), 256>>>(xz, Wconv, bconv, xc, xch);

    // 3) dt/B/C projections
    gemm_fp16<<<dim3(DI / BN, M / BM), NTHR, GEMM_SMEM>>>(xch, Wdth, dtp, DI, DI);
    gemm_fp16<<<dim3(DI / BN, M / BM), NTHR, GEMM_SMEM>>>(xch, WBh,  Bpp, DI, DI);
    gemm_fp16<<<dim3(DI / BN, M / BM), NTHR, GEMM_SMEM>>>(xch, WCh,  Cpp, DI, DI);

    // 4) chunked scan (3 passes)
    scan_chunks<<<(BB * NCHUNK * DI) / 256, 256>>>(xc, dtp, Bpp, bdt, A_log, Aprod, Hend);
    scan_carry <<<(BB * DI) / 256, 256>>>(Aprod, Hend, Carry);
    scan_out   <<<(BB * NCHUNK * DI) / 256, 256>>>(xz, xc, dtp, Bpp, Cpp, bdt, A_log,
                                                   Carry, yh);

    // 5) out_proj
    gemm_fp16<<<dim3(DM / BN, M / BM), NTHR, GEMM_SMEM>>>(yh, Woh, out, DI, DM);
}

// round 13
// speedup vs baseline: 6.5755x; 1.0897x over previous
#include <cuda_runtime.h>
#include <cuda_fp16.h>
#include <mma.h>
#include <cstdint>

using namespace nvcuda;

#define BB 4
#define LL 4096
#define DM 1024
#define DI 2048
#define MTOT (BB * LL)          // 16384
#define NCHUNK 16
#define LCH (LL / NCHUNK)       // 256
#define N3 (3 * DI)             // 6144: fused dt|B|C output width

// ---------------------------------------------------------------------------
// Scratch (device globals; allocation is forbidden in kernel_launch)
// ---------------------------------------------------------------------------
__device__ __align__(1024) float g_xz   [(size_t)MTOT * (2 * DI)]; // in_proj out
__device__ __align__(1024) float g_xc   [(size_t)MTOT * DI];       // conv out fp32
__device__ __align__(1024) float g_dtBC [(size_t)MTOT * N3];       // fused proj out
__device__ __align__(1024) float g_a    [(size_t)MTOT * DI];       // decay coeff
__device__ __align__(1024) float g_beta [(size_t)MTOT * DI];       // input term

__device__ __align__(1024) __half g_xch[(size_t)MTOT * DI];        // conv out fp16
__device__ __align__(1024) __half g_yh [(size_t)MTOT * DI];        // scan out fp16
__device__ __align__(1024) __half g_xh [(size_t)MTOT * DM];        // x fp16
__device__ __align__(1024) __half g_Wih [(size_t)2 * DI * DM];
__device__ __align__(1024) __half g_Wcat[(size_t)N3 * DI];         // [Wdt;WB;WC]
__device__ __align__(1024) __half g_Woh [(size_t)DM * DI];

__device__ float g_Aprod[BB * NCHUNK * DI];
__device__ float g_Hend [BB * NCHUNK * DI];
__device__ float g_Carry[BB * NCHUNK * DI];

// ---------------------------------------------------------------------------
// helpers
// ---------------------------------------------------------------------------
__device__ __forceinline__ void cp16h(__half* dst, const __half* src) {
    unsigned s = (unsigned)__cvta_generic_to_shared(dst);
    asm volatile("cp.async.cg.shared.global [%0], [%1], 16;" ::"r"(s), "l"(src));
}

// ---------------------------------------------------------------------------
// GEMM: C[M,N] = A[M,K] * W[N,K]^T  (fp16 HMMA m16n16k16, fp32 accumulate)
//   128x128x64 block, 4 warps (2x2), warp tile 64x64.
//   3-stage cp.async pipeline, 110.6KB smem -> 2 CTAs/SM.
//   SSTH=72 halfs (144B pitch): ldmatrix row banks 36r mod 32 all-distinct.
// ---------------------------------------------------------------------------
#define BM 128
#define BN 128
#define BK 64
#define SSTH 72
#define NSTG 3
#define NTHR 128
#define STAGEH ((BM + BN) * SSTH)                        // halfs per stage
#define GEMM_SMEM (NSTG * STAGEH * (int)sizeof(__half))  // 110592 B

__device__ __forceinline__ void load_stage(__half* sbase, const __half* A,
                                           const __half* W, int kt, int K,
                                           int mBase, int nBase, int tid) {
    const __half* Ab = A + (size_t)mBase * K + (size_t)kt * BK;
    const __half* Wb = W + (size_t)nBase * K + (size_t)kt * BK;
    // (128+128) rows x 64 halfs(128B) = 2048 chunks of 16B; 128 thr -> 16 each
#pragma unroll
    for (int i = 0; i < 16; i++) {
        int chunk = tid + i * NTHR;         // 0..2047
        int tile  = chunk >> 10;            // 0: A, 1: W
        int rem   = chunk & 1023;
        int row   = rem >> 3;               // 0..127
        int col   = (rem & 7) << 3;         // 0,8,...,56 (halfs)
        const __half* src = (tile ? Wb : Ab) + (size_t)row * K + col;
        __half* dst = sbase + tile * (BM * SSTH) + row * SSTH + col;
        cp16h(dst, src);
    }
    asm volatile("cp.async.commit_group;" ::: "memory");
}

__global__ __launch_bounds__(NTHR, 2) void gemm_fp16(const __half* __restrict__ A,
                                                     const __half* __restrict__ W,
                                                     float* __restrict__ C,
                                                     int K, int N) {
    extern __shared__ __half smem[];
    const int tid   = threadIdx.x;
    const int warp  = tid >> 5;
    const int wm    = warp & 1;             // 2 warp rows -> 64 M each
    const int wn    = warp >> 1;            // 2 warp cols -> 64 N each
    const int mBase = blockIdx.y * BM;
    const int nBase = blockIdx.x * BN;

    wmma::fragment<wmma::accumulator, 16, 16, 16, float> acc[4][4];
#pragma unroll
    for (int i = 0; i < 4; i++)
#pragma unroll
        for (int j = 0; j < 4; j++) wmma::fill_fragment(acc[i][j], 0.0f);

    const int KT = K / BK;

    // prologue: stages 0 and 1 in flight
    load_stage(smem + 0 * STAGEH, A, W, 0, K, mBase, nBase, tid);
    load_stage(smem + 1 * STAGEH, A, W, 1, K, mBase, nBase, tid);

    for (int kt = 0; kt < KT; kt++) {
        if (kt + 1 < KT) asm volatile("cp.async.wait_group 1;" ::: "memory");
        else             asm volatile("cp.async.wait_group 0;" ::: "memory");
        // barrier: stage kt visible; all warps done with stage kt-1 whose
        // slot (kt+2)%3 is refilled below
        __syncthreads();

        if (kt + 2 < KT)
            load_stage(smem + ((kt + 2) % NSTG) * STAGEH, A, W, kt + 2, K,
                       mBase, nBase, tid);

        const __half* As = smem + (kt % NSTG) * STAGEH;
        const __half* Bs = As + BM * SSTH;

#pragma unroll
        for (int kk = 0; kk < BK / 16; kk++) {
            wmma::fragment<wmma::matrix_a, 16, 16, 16, half, wmma::row_major> af[4];
            wmma::fragment<wmma::matrix_b, 16, 16, 16, half, wmma::col_major> bf[4];
#pragma unroll
            for (int i = 0; i < 4; i++)
                wmma::load_matrix_sync(af[i], As + (wm * 64 + i * 16) * SSTH + kk * 16, SSTH);
#pragma unroll
            for (int j = 0; j < 4; j++)
                wmma::load_matrix_sync(bf[j], Bs + (wn * 64 + j * 16) * SSTH + kk * 16, SSTH);
#pragma unroll
            for (int i = 0; i < 4; i++)
#pragma unroll
                for (int j = 0; j < 4; j++)
                    wmma::mma_sync(acc[i][j], af[i], bf[j], acc[i][j]);
        }
    }

#pragma unroll
    for (int i = 0; i < 4; i++)
#pragma unroll
        for (int j = 0; j < 4; j++) {
            size_t row = (size_t)(mBase + wm * 64 + i * 16);
            int    col = nBase + wn * 64 + j * 16;
            wmma::store_matrix_sync(C + row * N + col, acc[i][j], N,
                                    wmma::mem_row_major);
        }
}

// ---------------------------------------------------------------------------
// fp32 -> fp16 producer (8 elements per thread, 16B stores)
// ---------------------------------------------------------------------------
__global__ void to_half_kernel(const float* __restrict__ in,
                               __half* __restrict__ out, size_t n) {
    size_t i = ((size_t)blockIdx.x * blockDim.x + threadIdx.x) * 8;
    if (i >= n) return;
    float4 a = *(const float4*)(in + i);
    float4 b = *(const float4*)(in + i + 4);
    __half2 h[4];
    h[0] = __floats2half2_rn(a.x, a.y);
    h[1] = __floats2half2_rn(a.z, a.w);
    h[2] = __floats2half2_rn(b.x, b.y);
    h[3] = __floats2half2_rn(b.z, b.w);
    *(uint4*)(out + i) = *(uint4*)h;
}

// ---------------------------------------------------------------------------
// depthwise causal conv1d (k=4) + bias + SiLU -> fp32 (scan) + fp16 (GEMM)
// ---------------------------------------------------------------------------
__global__ void conv_silu_kernel(const float* __restrict__ xz,
                                 const float* __restrict__ Wc,
                                 const float* __restrict__ bc,
                                 float* __restrict__ xc,
                                 __half* __restrict__ xch) {
    size_t idx = (size_t)blockIdx.x * blockDim.x + threadIdx.x;
    if (idx >= (size_t)MTOT * DI) return;
    int d     = (int)(idx % DI);
    size_t bl = idx / DI;
    int l     = (int)(bl % LL);

    const float* xp = xz + bl * (size_t)(2 * DI) + d;
    float acc = bc[d];
#pragma unroll
    for (int j = 0; j < 4; j++) {
        int ll = l - 3 + j;
        if (ll >= 0) acc += Wc[d * 4 + j] * xp[(ptrdiff_t)(j - 3) * (2 * DI)];
    }
    float r = acc * __fdividef(1.0f, 1.0f + __expf(-acc));
    xc[idx]  = r;
    xch[idx] = __float2half_rn(r);
}

// ---------------------------------------------------------------------------
// Chunked SSM scan (3 passes). Pass 1 computes and STORES the recurrence
// coefficients a_t, beta_t; pass 3 only replays h = a*h + beta and applies
// the output gate. Arithmetic matches the serial recurrence.
// ---------------------------------------------------------------------------
__device__ __forceinline__ float sp_f(float x) {        // softplus (fast)
    return (x > 20.0f) ? x : __logf(1.0f + __expf(x));
}
__device__ __forceinline__ float sig_f(float x) {
    return __fdividef(1.0f, 1.0f + __expf(-x));
}
__device__ __forceinline__ float tanh_f(float x) {      // exact formula, 1 EX2
    float xc_ = fminf(fmaxf(x, -15.0f), 15.0f);
    float e   = __expf(2.0f * xc_);
    return __fdividef(e - 1.0f, e + 1.0f);
}

__global__ void scan_chunks(const float* __restrict__ xc,
                            const float* __restrict__ dtBC,
                            const float* __restrict__ bdt,
                            const float* __restrict__ A_log,
                            float* __restrict__ a_arr,
                            float* __restrict__ beta_arr,
                            float* __restrict__ Aprod, float* __restrict__ Hend) {
    int idx = blockIdx.x * blockDim.x + threadIdx.x;    // BB*NCHUNK*DI
    if (idx >= BB * NCHUNK * DI) return;
    int d  = idx % DI;
    int bc = idx / DI;
    int c  = bc % NCHUNK;
    int b  = bc / NCHUNK;

    const float bd = bdt[d];
    const float Ad = -expf(A_log[d]);
    int l0 = c * LCH;
    size_t off  = ((size_t)b * LL + l0) * DI + d;             // xc/a/beta index
    size_t off3 = ((size_t)b * LL + l0) * N3 + d;             // dtBC index

    float uprev = 0.0f;
    if (l0 > 0) uprev = xc[off - DI] * sig_f(dtBC[off3 - N3 + DI]);

    float h = 0.0f, A = 1.0f;
    for (int l = 0; l < LCH; l++) {
        float dtv = sp_f(dtBC[off3] + bd);
        float la  = fminf(fmaxf(Ad * dtv, -10.0f), -0.0001f);
        float a   = __expf(la);
        float u   = xc[off] * sig_f(dtBC[off3 + DI]);
        float bta = dtv * 0.5f * (uprev + u);
        h = a * h + bta;
        A *= a;
        uprev = u;
        a_arr[off]    = a;
        beta_arr[off] = bta;
        off  += DI;
        off3 += N3;
    }
    Aprod[idx] = A;
    Hend[idx]  = h;
}

__global__ void scan_carry(const float* __restrict__ Aprod,
                           const float* __restrict__ Hend,
                           float* __restrict__ Carry) {
    int t = blockIdx.x * blockDim.x + threadIdx.x;      // BB*DI
    if (t >= BB * DI) return;
    int d = t % DI, b = t / DI;
    float h = 0.0f;
#pragma unroll
    for (int c = 0; c < NCHUNK; c++) {
        size_t i = ((size_t)b * NCHUNK + c) * DI + d;
        Carry[i] = h;
        h = Aprod[i] * h + Hend[i];
    }
}

__global__ void scan_out(const float* __restrict__ xz,
                         const float* __restrict__ dtBC,
                         const float* __restrict__ a_arr,
                         const float* __restrict__ beta_arr,
                         const float* __restrict__ Carry,
                         __half* __restrict__ yh) {
    int idx = blockIdx.x * blockDim.x + threadIdx.x;
    if (idx >= BB * NCHUNK * DI) return;
    int d  = idx % DI;
    int bc = idx / DI;
    int c  = bc % NCHUNK;
    int b  = bc / NCHUNK;

    int l0 = c * LCH;
    size_t off  = ((size_t)b * LL + l0) * DI + d;
    size_t off3 = ((size_t)b * LL + l0) * N3 + 2 * DI + d;    // C-proj column
    size_t zoff = ((size_t)b * LL + l0) * (size_t)(2 * DI) + DI + d;

    float h = Carry[idx];
    for (int l = 0; l < LCH; l++) {
        h = a_arr[off] * h + beta_arr[off];

        float Ct = tanh_f(dtBC[off3]);
        float zv = xz[zoff];
        float yv = h * Ct * (zv * sig_f(zv));
        yh[off]  = __float2half_rn(yv);

        off  += DI;
        off3 += N3;
        zoff += 2 * DI;
    }
}

// ---------------------------------------------------------------------------
// Launch
// ---------------------------------------------------------------------------
extern "C" void kernel_launch(void* const* d_in, const int* in_sizes, int n_in,
                              void* d_out, int out_size) {
    const float* x     = (const float*)d_in[0];
    const float* Wi    = (const float*)d_in[1];
    const float* Wconv = (const float*)d_in[2];
    const float* bconv = (const float*)d_in[3];
    const float* Wdt   = (const float*)d_in[4];
    const float* bdt   = (const float*)d_in[5];
    const float* WB    = (const float*)d_in[6];
    const float* WC    = (const float*)d_in[7];
    const float* Wo    = (const float*)d_in[8];
    const float* A_log = (const float*)d_in[9];
    float*       out   = (float*)d_out;

    float *xz, *xc, *dtBC, *a_arr, *beta_arr, *Aprod, *Hend, *Carry;
    __half *xh, *xch, *yh, *Wih, *Wcat, *Woh;

    cudaGetSymbolAddress((void**)&xz,    g_xz);
    cudaGetSymbolAddress((void**)&xc,    g_xc);
    cudaGetSymbolAddress((void**)&dtBC,  g_dtBC);
    cudaGetSymbolAddress((void**)&a_arr, g_a);
    cudaGetSymbolAddress((void**)&beta_arr, g_beta);
    cudaGetSymbolAddress((void**)&xh,    g_xh);
    cudaGetSymbolAddress((void**)&xch,   g_xch);
    cudaGetSymbolAddress((void**)&yh,    g_yh);
    cudaGetSymbolAddress((void**)&Wih,   g_Wih);
    cudaGetSymbolAddress((void**)&Wcat,  g_Wcat);
    cudaGetSymbolAddress((void**)&Woh,   g_Woh);
    cudaGetSymbolAddress((void**)&Aprod, g_Aprod);
    cudaGetSymbolAddress((void**)&Hend,  g_Hend);
    cudaGetSymbolAddress((void**)&Carry, g_Carry);

    cudaFuncSetAttribute(gemm_fp16, cudaFuncAttributeMaxDynamicSharedMemorySize,
                         GEMM_SMEM);

    const int M = MTOT;

    // 0) fp16 conversion of GEMM operands (Wdt|WB|WC concatenated along N)
    {
        size_t n;
        n = (size_t)M * DM;
        to_half_kernel<<<(unsigned)(n / 8 / 256), 256>>>(x, xh, n);
        n = (size_t)2 * DI * DM;
        to_half_kernel<<<(unsigned)(n / 8 / 256), 256>>>(Wi, Wih, n);
        n = (size_t)DI * DI;
        to_half_kernel<<<(unsigned)(n / 8 / 256), 256>>>(Wdt, Wcat, n);
        to_half_kernel<<<(unsigned)(n / 8 / 256), 256>>>(WB,  Wcat + (size_t)DI * DI, n);
        to_half_kernel<<<(unsigned)(n / 8 / 256), 256>>>(WC,  Wcat + (size_t)2 * DI * DI, n);
        n = (size_t)DM * DI;
        to_half_kernel<<<(unsigned)(n / 8 / 256), 256>>>(Wo, Woh, n);
    }

    // 1) in_proj: xz[M, 4096] = xh @ Wih^T
    gemm_fp16<<<dim3((2 * DI) / BN, M / BM), NTHR, GEMM_SMEM>>>(xh, Wih, xz, DM, 2 * DI);

    // 2) depthwise causal conv + SiLU
    conv_silu_kernel<<<(unsigned)(((size_t)M * DI) / 256), 256>>>(xz, Wconv, bconv, xc, xch);

    // 3) fused dt|B|C projection: dtBC[M, 6144] = xch @ Wcat^T
    gemm_fp16<<<dim3(N3 / BN, M / BM), NTHR, GEMM_SMEM>>>(xch, Wcat, dtBC, DI, N3);

    // 4) chunked scan (3 passes; pass 1 stores coefficients)
    scan_chunks<<<(BB * NCHUNK * DI) / 256, 256>>>(xc, dtBC, bdt, A_log,
                                                   a_arr, beta_arr, Aprod, Hend);
    scan_carry <<<(BB * DI) / 256, 256>>>(Aprod, Hend, Carry);
    scan_out   <<<(BB * NCHUNK * DI) / 256, 256>>>(xz, dtBC, a_arr, beta_arr,
                                                   Carry, yh);

    // 5) out_proj
    gemm_fp16<<<dim3(DM / BN, M / BM), NTHR, GEMM_SMEM>>>(yh, Woh, out, DI, DM);
}

// round 14
// speedup vs baseline: 6.7113x; 1.0206x over previous
#include <cuda_runtime.h>
#include <cuda_fp16.h>
#include <mma.h>
#include <cstdint>

using namespace nvcuda;

#define BB 4
#define LL 4096
#define DM 1024
#define DI 2048
#define MTOT (BB * LL)          // 16384
#define NCHUNK 16
#define LCH (LL / NCHUNK)       // 256
#define N3 (3 * DI)             // 6144: fused dt|B|C output width

// ---------------------------------------------------------------------------
// Scratch (device globals; allocation is forbidden in kernel_launch)
// ---------------------------------------------------------------------------
__device__ __align__(1024) __half g_xz  [(size_t)MTOT * (2 * DI)]; // in_proj out (fp16)
__device__ __align__(1024) __half g_dtBC[(size_t)MTOT * N3];       // fused proj out (fp16)
__device__ __align__(1024) float  g_a   [(size_t)MTOT * DI];       // decay coeff (fp32)
__device__ __align__(1024) float  g_beta[(size_t)MTOT * DI];       // input term (fp32)

__device__ __align__(1024) __half g_xch[(size_t)MTOT * DI];        // conv out fp16
__device__ __align__(1024) __half g_yh [(size_t)MTOT * DI];        // scan out fp16
__device__ __align__(1024) __half g_xh [(size_t)MTOT * DM];        // x fp16
__device__ __align__(1024) __half g_Wih [(size_t)2 * DI * DM];
__device__ __align__(1024) __half g_Wcat[(size_t)N3 * DI];         // [Wdt;WB;WC]
__device__ __align__(1024) __half g_Woh [(size_t)DM * DI];

__device__ float g_Aprod[BB * NCHUNK * DI];
__device__ float g_Hend [BB * NCHUNK * DI];
__device__ float g_Carry[BB * NCHUNK * DI];

// ---------------------------------------------------------------------------
// helpers
// ---------------------------------------------------------------------------
__device__ __forceinline__ void cp16h(__half* dst, const __half* src) {
    unsigned s = (unsigned)__cvta_generic_to_shared(dst);
    asm volatile("cp.async.cg.shared.global [%0], [%1], 16;" ::"r"(s), "l"(src));
}

// ---------------------------------------------------------------------------
// GEMM: C[M,N] = A[M,K] * W[N,K]^T  (fp16 HMMA m16n16k16, fp32 accumulate)
//   Output type templated: fp32 (final out_proj) or fp16 (intermediates).
//   128x128x64 block, 4 warps (2x2), warp tile 64x64.
//   3-stage cp.async pipeline, 110.6KB smem -> 2 CTAs/SM.
//   SSTH=72 halfs (144B pitch): ldmatrix row banks 36r mod 32 all-distinct.
// ---------------------------------------------------------------------------
#define BM 128
#define BN 128
#define BK 64
#define SSTH 72
#define NSTG 3
#define NTHR 128
#define STAGEH ((BM + BN) * SSTH)                        // halfs per stage
#define GEMM_SMEM (NSTG * STAGEH * (int)sizeof(__half))  // 110592 B

__device__ __forceinline__ void load_stage(__half* sbase, const __half* A,
                                           const __half* W, int kt, int K,
                                           int mBase, int nBase, int tid) {
    const __half* Ab = A + (size_t)mBase * K + (size_t)kt * BK;
    const __half* Wb = W + (size_t)nBase * K + (size_t)kt * BK;
    // (128+128) rows x 64 halfs(128B) = 2048 chunks of 16B; 128 thr -> 16 each
#pragma unroll
    for (int i = 0; i < 16; i++) {
        int chunk = tid + i * NTHR;         // 0..2047
        int tile  = chunk >> 10;            // 0: A, 1: W
        int rem   = chunk & 1023;
        int row   = rem >> 3;               // 0..127
        int col   = (rem & 7) << 3;         // 0,8,...,56 (halfs)
        const __half* src = (tile ? Wb : Ab) + (size_t)row * K + col;
        __half* dst = sbase + tile * (BM * SSTH) + row * SSTH + col;
        cp16h(dst, src);
    }
    asm volatile("cp.async.commit_group;" ::: "memory");
}

template <typename OutT>
__global__ __launch_bounds__(NTHR, 2) void gemm_fp16(const __half* __restrict__ A,
                                                     const __half* __restrict__ W,
                                                     OutT* __restrict__ C,
                                                     int K, int N) {
    extern __shared__ __half smem[];
    const int tid   = threadIdx.x;
    const int warp  = tid >> 5;
    const int wm    = warp & 1;             // 2 warp rows -> 64 M each
    const int wn    = warp >> 1;            // 2 warp cols -> 64 N each
    const int mBase = blockIdx.y * BM;
    const int nBase = blockIdx.x * BN;

    wmma::fragment<wmma::accumulator, 16, 16, 16, float> acc[4][4];
#pragma unroll
    for (int i = 0; i < 4; i++)
#pragma unroll
        for (int j = 0; j < 4; j++) wmma::fill_fragment(acc[i][j], 0.0f);

    const int KT = K / BK;

    // prologue: stages 0 and 1 in flight
    load_stage(smem + 0 * STAGEH, A, W, 0, K, mBase, nBase, tid);
    load_stage(smem + 1 * STAGEH, A, W, 1, K, mBase, nBase, tid);

    for (int kt = 0; kt < KT; kt++) {
        if (kt + 1 < KT) asm volatile("cp.async.wait_group 1;" ::: "memory");
        else             asm volatile("cp.async.wait_group 0;" ::: "memory");
        // barrier: stage kt visible; all warps done with stage kt-1 whose
        // slot (kt+2)%3 is refilled below
        __syncthreads();

        if (kt + 2 < KT)
            load_stage(smem + ((kt + 2) % NSTG) * STAGEH, A, W, kt + 2, K,
                       mBase, nBase, tid);

        const __half* As = smem + (kt % NSTG) * STAGEH;
        const __half* Bs = As + BM * SSTH;

#pragma unroll
        for (int kk = 0; kk < BK / 16; kk++) {
            wmma::fragment<wmma::matrix_a, 16, 16, 16, half, wmma::row_major> af[4];
            wmma::fragment<wmma::matrix_b, 16, 16, 16, half, wmma::col_major> bf[4];
#pragma unroll
            for (int i = 0; i < 4; i++)
                wmma::load_matrix_sync(af[i], As + (wm * 64 + i * 16) * SSTH + kk * 16, SSTH);
#pragma unroll
            for (int j = 0; j < 4; j++)
                wmma::load_matrix_sync(bf[j], Bs + (wn * 64 + j * 16) * SSTH + kk * 16, SSTH);
#pragma unroll
            for (int i = 0; i < 4; i++)
#pragma unroll
                for (int j = 0; j < 4; j++)
                    wmma::mma_sync(acc[i][j], af[i], bf[j], acc[i][j]);
        }
    }

#pragma unroll
    for (int i = 0; i < 4; i++)
#pragma unroll
        for (int j = 0; j < 4; j++) {
            size_t row = (size_t)(mBase + wm * 64 + i * 16);
            int    col = nBase + wn * 64 + j * 16;
            if constexpr (sizeof(OutT) == 2) {
                wmma::fragment<wmma::accumulator, 16, 16, 16, half> hacc;
#pragma unroll
                for (int t = 0; t < hacc.num_elements; t++)
                    hacc.x[t] = __float2half_rn(acc[i][j].x[t]);
                wmma::store_matrix_sync((__half*)C + row * N + col, hacc, N,
                                        wmma::mem_row_major);
            } else {
                wmma::store_matrix_sync((float*)C + row * N + col, acc[i][j], N,
                                        wmma::mem_row_major);
            }
        }
}

// ---------------------------------------------------------------------------
// fp32 -> fp16 producer (8 elements per thread, 16B stores)
// ---------------------------------------------------------------------------
__global__ void to_half_kernel(const float* __restrict__ in,
                               __half* __restrict__ out, size_t n) {
    size_t i = ((size_t)blockIdx.x * blockDim.x + threadIdx.x) * 8;
    if (i >= n) return;
    float4 a = *(const float4*)(in + i);
    float4 b = *(const float4*)(in + i + 4);
    __half2 h[4];
    h[0] = __floats2half2_rn(a.x, a.y);
    h[1] = __floats2half2_rn(a.z, a.w);
    h[2] = __floats2half2_rn(b.x, b.y);
    h[3] = __floats2half2_rn(b.z, b.w);
    *(uint4*)(out + i) = *(uint4*)h;
}

// ---------------------------------------------------------------------------
// depthwise causal conv1d (k=4) + bias + SiLU; fp16 in, fp32 math, fp16 out
// ---------------------------------------------------------------------------
__global__ void conv_silu_kernel(const __half* __restrict__ xz,
                                 const float* __restrict__ Wc,
                                 const float* __restrict__ bc,
                                 __half* __restrict__ xch) {
    size_t idx = (size_t)blockIdx.x * blockDim.x + threadIdx.x;
    if (idx >= (size_t)MTOT * DI) return;
    int d     = (int)(idx % DI);
    size_t bl = idx / DI;
    int l     = (int)(bl % LL);

    const __half* xp = xz + bl * (size_t)(2 * DI) + d;
    float acc = bc[d];
#pragma unroll
    for (int j = 0; j < 4; j++) {
        int ll = l - 3 + j;
        if (ll >= 0)
            acc += Wc[d * 4 + j] * __half2float(xp[(ptrdiff_t)(j - 3) * (2 * DI)]);
    }
    float r = acc * __fdividef(1.0f, 1.0f + __expf(-acc));
    xch[idx] = __float2half_rn(r);
}

// ---------------------------------------------------------------------------
// Chunked SSM scan (3 passes). Pass 1 computes and stores the recurrence
// coefficients a_t, beta_t in fp32 (a errors would compound over the scan);
// pass 3 replays h = a*h + beta and applies the output gate.
// ---------------------------------------------------------------------------
__device__ __forceinline__ float sp_f(float x) {        // softplus (fast)
    return (x > 20.0f) ? x : __logf(1.0f + __expf(x));
}
__device__ __forceinline__ float sig_f(float x) {
    return __fdividef(1.0f, 1.0f + __expf(-x));
}
__device__ __forceinline__ float tanh_f(float x) {      // exact formula, 1 EX2
    float xc_ = fminf(fmaxf(x, -15.0f), 15.0f);
    float e   = __expf(2.0f * xc_);
    return __fdividef(e - 1.0f, e + 1.0f);
}

__global__ void scan_chunks(const __half* __restrict__ xch,
                            const __half* __restrict__ dtBC,
                            const float* __restrict__ bdt,
                            const float* __restrict__ A_log,
                            float* __restrict__ a_arr,
                            float* __restrict__ beta_arr,
                            float* __restrict__ Aprod, float* __restrict__ Hend) {
    int idx = blockIdx.x * blockDim.x + threadIdx.x;    // BB*NCHUNK*DI
    if (idx >= BB * NCHUNK * DI) return;
    int d  = idx % DI;
    int bc = idx / DI;
    int c  = bc % NCHUNK;
    int b  = bc / NCHUNK;

    const float bd = bdt[d];
    const float Ad = -expf(A_log[d]);
    int l0 = c * LCH;
    size_t off  = ((size_t)b * LL + l0) * DI + d;             // xch/a/beta index
    size_t off3 = ((size_t)b * LL + l0) * N3 + d;             // dtBC index

    float uprev = 0.0f;
    if (l0 > 0)
        uprev = __half2float(xch[off - DI]) *
                sig_f(__half2float(dtBC[off3 - N3 + DI]));

    float h = 0.0f, A = 1.0f;
    for (int l = 0; l < LCH; l++) {
        float dtv = sp_f(__half2float(dtBC[off3]) + bd);
        float la  = fminf(fmaxf(Ad * dtv, -10.0f), -0.0001f);
        float a   = __expf(la);
        float u   = __half2float(xch[off]) * sig_f(__half2float(dtBC[off3 + DI]));
        float bta = dtv * 0.5f * (uprev + u);
        h = a * h + bta;
        A *= a;
        uprev = u;
        a_arr[off]    = a;
        beta_arr[off] = bta;
        off  += DI;
        off3 += N3;
    }
    Aprod[idx] = A;
    Hend[idx]  = h;
}

__global__ void scan_carry(const float* __restrict__ Aprod,
                           const float* __restrict__ Hend,
                           float* __restrict__ Carry) {
    int t = blockIdx.x * blockDim.x + threadIdx.x;      // BB*DI
    if (t >= BB * DI) return;
    int d = t % DI, b = t / DI;
    float h = 0.0f;
#pragma unroll
    for (int c = 0; c < NCHUNK; c++) {
        size_t i = ((size_t)b * NCHUNK + c) * DI + d;
        Carry[i] = h;
        h = Aprod[i] * h + Hend[i];
    }
}

__global__ void scan_out(const __half* __restrict__ xz,
                         const __half* __restrict__ dtBC,
                         const float* __restrict__ a_arr,
                         const float* __restrict__ beta_arr,
                         const float* __restrict__ Carry,
                         __half* __restrict__ yh) {
    int idx = blockIdx.x * blockDim.x + threadIdx.x;
    if (idx >= BB * NCHUNK * DI) return;
    int d  = idx % DI;
    int bc = idx / DI;
    int c  = bc % NCHUNK;
    int b  = bc / NCHUNK;

    int l0 = c * LCH;
    size_t off  = ((size_t)b * LL + l0) * DI + d;
    size_t off3 = ((size_t)b * LL + l0) * N3 + 2 * DI + d;    // C-proj column
    size_t zoff = ((size_t)b * LL + l0) * (size_t)(2 * DI) + DI + d;

    float h = Carry[idx];
    for (int l = 0; l < LCH; l++) {
        h = a_arr[off] * h + beta_arr[off];

        float Ct = tanh_f(__half2float(dtBC[off3]));
        float zv = __half2float(xz[zoff]);
        float yv = h * Ct * (zv * sig_f(zv));
        yh[off]  = __float2half_rn(yv);

        off  += DI;
        off3 += N3;
        zoff += 2 * DI;
    }
}

// ---------------------------------------------------------------------------
// Launch
// ---------------------------------------------------------------------------
extern "C" void kernel_launch(void* const* d_in, const int* in_sizes, int n_in,
                              void* d_out, int out_size) {
    const float* x     = (const float*)d_in[0];
    const float* Wi    = (const float*)d_in[1];
    const float* Wconv = (const float*)d_in[2];
    const float* bconv = (const float*)d_in[3];
    const float* Wdt   = (const float*)d_in[4];
    const float* bdt   = (const float*)d_in[5];
    const float* WB    = (const float*)d_in[6];
    const float* WC    = (const float*)d_in[7];
    const float* Wo    = (const float*)d_in[8];
    const float* A_log = (const float*)d_in[9];
    float*       out   = (float*)d_out;

    float *a_arr, *beta_arr, *Aprod, *Hend, *Carry;
    __half *xz, *dtBC, *xh, *xch, *yh, *Wih, *Wcat, *Woh;

    cudaGetSymbolAddress((void**)&xz,    g_xz);
    cudaGetSymbolAddress((void**)&dtBC,  g_dtBC);
    cudaGetSymbolAddress((void**)&a_arr, g_a);
    cudaGetSymbolAddress((void**)&beta_arr, g_beta);
    cudaGetSymbolAddress((void**)&xh,    g_xh);
    cudaGetSymbolAddress((void**)&xch,   g_xch);
    cudaGetSymbolAddress((void**)&yh,    g_yh);
    cudaGetSymbolAddress((void**)&Wih,   g_Wih);
    cudaGetSymbolAddress((void**)&Wcat,  g_Wcat);
    cudaGetSymbolAddress((void**)&Woh,   g_Woh);
    cudaGetSymbolAddress((void**)&Aprod, g_Aprod);
    cudaGetSymbolAddress((void**)&Hend,  g_Hend);
    cudaGetSymbolAddress((void**)&Carry, g_Carry);

    cudaFuncSetAttribute(gemm_fp16<__half>,
                         cudaFuncAttributeMaxDynamicSharedMemorySize, GEMM_SMEM);
    cudaFuncSetAttribute(gemm_fp16<float>,
                         cudaFuncAttributeMaxDynamicSharedMemorySize, GEMM_SMEM);

    const int M = MTOT;

    // 0) fp16 conversion of GEMM operands (Wdt|WB|WC concatenated along N)
    {
        size_t n;
        n = (size_t)M * DM;
        to_half_kernel<<<(unsigned)(n / 8 / 256), 256>>>(x, xh, n);
        n = (size_t)2 * DI * DM;
        to_half_kernel<<<(unsigned)(n / 8 / 256), 256>>>(Wi, Wih, n);
        n = (size_t)DI * DI;
        to_half_kernel<<<(unsigned)(n / 8 / 256), 256>>>(Wdt, Wcat, n);
        to_half_kernel<<<(unsigned)(n / 8 / 256), 256>>>(WB,  Wcat + (size_t)DI * DI, n);
        to_half_kernel<<<(unsigned)(n / 8 / 256), 256>>>(WC,  Wcat + (size_t)2 * DI * DI, n);
        n = (size_t)DM * DI;
        to_half_kernel<<<(unsigned)(n / 8 / 256), 256>>>(Wo, Woh, n);
    }

    // 1) in_proj: xz[M, 4096] (fp16) = xh @ Wih^T
    gemm_fp16<__half><<<dim3((2 * DI) / BN, M / BM), NTHR, GEMM_SMEM>>>(
        xh, Wih, xz, DM, 2 * DI);

    // 2) depthwise causal conv + SiLU -> xch (fp16)
    conv_silu_kernel<<<(unsigned)(((size_t)M * DI) / 256), 256>>>(xz, Wconv, bconv, xch);

    // 3) fused dt|B|C projection: dtBC[M, 6144] (fp16) = xch @ Wcat^T
    gemm_fp16<__half><<<dim3(N3 / BN, M / BM), NTHR, GEMM_SMEM>>>(
        xch, Wcat, dtBC, DI, N3);

    // 4) chunked scan (3 passes; pass 1 stores fp32 coefficients)
    scan_chunks<<<(BB * NCHUNK * DI) / 256, 256>>>(xch, dtBC, bdt, A_log,
                                                   a_arr, beta_arr, Aprod, Hend);
    scan_carry <<<(BB * DI) / 256, 256>>>(Aprod, Hend, Carry);
    scan_out   <<<(BB * NCHUNK * DI) / 256, 256>>>(xz, dtBC, a_arr, beta_arr,
                                                   Carry, yh);

    // 5) out_proj (fp32 out, final result)
    gemm_fp16<float><<<dim3(DM / BN, M / BM), NTHR, GEMM_SMEM>>>(
        yh, Woh, out, DI, DM);
}